// round 2
// baseline (speedup 1.0000x reference)
#include <cuda_runtime.h>
#include <cuda_bf16.h>
#include <math.h>

// Problem constants
#define B_SZ   2
#define S_LEN  2048
#define HID    2048
#define NH     16
#define NKV    4
#define DH     128
#define GROUPS (NH / NKV)
#define ROWS   (B_SZ * S_LEN)        // 4096

// Scratch (static device globals; allocation-free)
__device__ float g_Q[ROWS * NH * DH];    // 4096 x 2048
__device__ float g_K[ROWS * NKV * DH];   // 4096 x 512
__device__ float g_V[ROWS * NKV * DH];   // 4096 x 512
__device__ float g_O[ROWS * NH * DH];    // 4096 x 2048

// ---------------------------------------------------------------------------
// SGEMM: C[M,N] = A[M,K] @ B[K,N], all row-major fp32.
// 128x128 block tile, BK=8, 256 threads, 8x8 micro-tile per thread.
// Requires M%128==0, N%128==0, K%8==0 (true for all our shapes).
// ---------------------------------------------------------------------------
__global__ __launch_bounds__(256) void sgemm128(
    const float* __restrict__ A, const float* __restrict__ B,
    float* __restrict__ C, int M, int N, int K)
{
    __shared__ float As[8][128];   // transposed A tile: As[k][m]
    __shared__ float Bs[8][128];   // Bs[k][n]

    const int tid = threadIdx.x;
    const int tx  = tid & 15;      // 0..15
    const int ty  = tid >> 4;      // 0..15
    const int bm  = blockIdx.y * 128;
    const int bn  = blockIdx.x * 128;

    const int aRow = tid >> 1;          // 0..127
    const int aCol = (tid & 1) * 4;     // 0 or 4
    const int bRow = tid >> 5;          // 0..7
    const int bCol = (tid & 31) * 4;    // 0..124

    const float* Aptr = A + (size_t)(bm + aRow) * K + aCol;
    const float* Bptr = B + (size_t)bRow * N + bn + bCol;

    float acc[8][8];
#pragma unroll
    for (int i = 0; i < 8; i++)
#pragma unroll
        for (int j = 0; j < 8; j++) acc[i][j] = 0.f;

    for (int k0 = 0; k0 < K; k0 += 8) {
        float4 av = *(const float4*)(Aptr + k0);
        As[aCol + 0][aRow] = av.x;
        As[aCol + 1][aRow] = av.y;
        As[aCol + 2][aRow] = av.z;
        As[aCol + 3][aRow] = av.w;
        float4 bv = *(const float4*)(Bptr + (size_t)k0 * N);
        *(float4*)&Bs[bRow][bCol] = bv;
        __syncthreads();

#pragma unroll
        for (int k = 0; k < 8; ++k) {
            float a[8], b[8];
            *(float4*)&a[0] = *(const float4*)&As[k][ty * 8];
            *(float4*)&a[4] = *(const float4*)&As[k][ty * 8 + 4];
            *(float4*)&b[0] = *(const float4*)&Bs[k][tx * 8];
            *(float4*)&b[4] = *(const float4*)&Bs[k][tx * 8 + 4];
#pragma unroll
            for (int i = 0; i < 8; i++)
#pragma unroll
                for (int j = 0; j < 8; j++)
                    acc[i][j] += a[i] * b[j];
        }
        __syncthreads();
    }

#pragma unroll
    for (int i = 0; i < 8; i++) {
        float* Crow = C + (size_t)(bm + ty * 8 + i) * N + bn + tx * 8;
        *(float4*)&Crow[0] = make_float4(acc[i][0], acc[i][1], acc[i][2], acc[i][3]);
        *(float4*)&Crow[4] = make_float4(acc[i][4], acc[i][5], acc[i][6], acc[i][7]);
    }
}

// ---------------------------------------------------------------------------
// RoPE (interleaved pairs) applied in-place to g_Q and g_K.
// freqs layout: [S, D/2, 2] => freqs[s*128 + 2*i] = cos, +1 = sin
// ---------------------------------------------------------------------------
__global__ __launch_bounds__(256) void rope_kernel(
    float* __restrict__ Q, float* __restrict__ Kt,
    const float* __restrict__ freqs)
{
    const int QP = ROWS * NH * (DH / 2);    // 4,194,304
    const int KP = ROWS * NKV * (DH / 2);   // 1,048,576
    int idx = blockIdx.x * blockDim.x + threadIdx.x;
    if (idx < QP) {
        int i   = idx & 63;
        int h   = (idx >> 6) & (NH - 1);
        int row = idx >> 10;                // /(16*64)
        int s   = row & (S_LEN - 1);
        float c  = freqs[s * 128 + 2 * i];
        float sn = freqs[s * 128 + 2 * i + 1];
        float* p = Q + (size_t)row * (NH * DH) + h * DH + 2 * i;
        float xr = p[0], xi = p[1];
        p[0] = xr * c - xi * sn;
        p[1] = xr * sn + xi * c;
    } else if (idx < QP + KP) {
        int j   = idx - QP;
        int i   = j & 63;
        int h   = (j >> 6) & (NKV - 1);
        int row = j >> 8;                   // /(4*64)
        int s   = row & (S_LEN - 1);
        float c  = freqs[s * 128 + 2 * i];
        float sn = freqs[s * 128 + 2 * i + 1];
        float* p = Kt + (size_t)row * (NKV * DH) + h * DH + 2 * i;
        float xr = p[0], xi = p[1];
        p[0] = xr * c - xi * sn;
        p[1] = xr * sn + xi * c;
    }
}

// ---------------------------------------------------------------------------
// Flash attention (fp32, causal, GQA). One block = 64 queries of one (b,h).
// 256 threads: thread (row = tid/4, cg = tid%4); owns output cols {4c+cg}.
// Online softmax over 64-key tiles, only tiles kt <= qt (causal skip).
// Smem: Qs[64][132], Ks[64][132], Vs[64][128], Ps[64][65]  = 116,992 B dyn.
// ---------------------------------------------------------------------------
#define BQ 64
#define BK 64
#define QPAD 132
#define PPAD 65

__global__ __launch_bounds__(256) void attn_kernel(
    const float* __restrict__ Q, const float* __restrict__ K,
    const float* __restrict__ V, float* __restrict__ O)
{
    extern __shared__ float sm[];
    float* Qs = sm;                       // 64*132
    float* Ks = Qs + BQ * QPAD;           // 64*132
    float* Vs = Ks + BK * QPAD;           // 64*128
    float* Ps = Vs + BK * DH;             // 64*65

    const int qt  = blockIdx.x;
    const int bh  = blockIdx.y;
    const int b   = bh / NH;
    const int h   = bh % NH;
    const int kvh = h / GROUPS;
    const int tid = threadIdx.x;
    const int row = tid >> 2;
    const int cg  = tid & 3;

    const float scale = 0.08838834764831845f;  // 1/sqrt(128)

    const size_t qbase = ((size_t)(b * S_LEN + qt * BQ)) * (NH * DH) + h * DH;
    // Load & pre-scale Q tile
    for (int t = tid; t < BQ * DH / 4; t += 256) {
        int r  = t >> 5;            // 32 float4 per row
        int c4 = (t & 31) * 4;
        float4 v = *(const float4*)(Q + qbase + (size_t)r * (NH * DH) + c4);
        v.x *= scale; v.y *= scale; v.z *= scale; v.w *= scale;
        *(float4*)&Qs[r * QPAD + c4] = v;
    }

    float m = -INFINITY, l = 0.f;
    float o[32];
#pragma unroll
    for (int c = 0; c < 32; c++) o[c] = 0.f;

    const size_t kbase = ((size_t)(b * S_LEN)) * (NKV * DH) + kvh * DH;
    const int q_global = qt * BQ + row;

    for (int kt = 0; kt <= qt; ++kt) {
        __syncthreads();  // previous iteration's consumers done before overwrite
        for (int t = tid; t < BK * DH / 4; t += 256) {
            int r  = t >> 5;
            int c4 = (t & 31) * 4;
            size_t g = kbase + (size_t)(kt * BK + r) * (NKV * DH) + c4;
            *(float4*)&Ks[r * QPAD + c4] = *(const float4*)(K + g);
            *(float4*)&Vs[r * DH + c4]   = *(const float4*)(V + g);
        }
        __syncthreads();

        // Scores for this thread's 16 keys (j = 4*jj + cg, strided: conflict-free)
        float s[16];
#pragma unroll
        for (int jj = 0; jj < 16; jj++) s[jj] = 0.f;
        for (int k = 0; k < DH; k++) {
            float qv = Qs[row * QPAD + k];
#pragma unroll
            for (int jj = 0; jj < 16; jj++)
                s[jj] += qv * Ks[(jj * 4 + cg) * QPAD + k];
        }

        if (kt == qt) {
#pragma unroll
            for (int jj = 0; jj < 16; jj++) {
                int jg = kt * BK + jj * 4 + cg;
                if (jg > q_global) s[jj] = -INFINITY;
            }
        }

        // Row max across this thread's 16, then across the 4-lane row group
        float tmax = s[0];
#pragma unroll
        for (int jj = 1; jj < 16; jj++) tmax = fmaxf(tmax, s[jj]);
        tmax = fmaxf(tmax, __shfl_xor_sync(0xffffffffu, tmax, 1));
        tmax = fmaxf(tmax, __shfl_xor_sync(0xffffffffu, tmax, 2));
        float mnew = fmaxf(m, tmax);
        float corr = expf(m - mnew);

        float psum = 0.f;
#pragma unroll
        for (int jj = 0; jj < 16; jj++) {
            float p = expf(s[jj] - mnew);
            s[jj] = p;
            psum += p;
        }
        psum += __shfl_xor_sync(0xffffffffu, psum, 1);
        psum += __shfl_xor_sync(0xffffffffu, psum, 2);
        l = l * corr + psum;
        m = mnew;
#pragma unroll
        for (int c = 0; c < 32; c++) o[c] *= corr;

        // P row is produced and consumed within the same warp -> __syncwarp
#pragma unroll
        for (int jj = 0; jj < 16; jj++) Ps[row * PPAD + jj * 4 + cg] = s[jj];
        __syncwarp();

        for (int j = 0; j < BK; j++) {
            float pv = Ps[row * PPAD + j];
#pragma unroll
            for (int c = 0; c < 32; c++)
                o[c] += pv * Vs[j * DH + c * 4 + cg];
        }
    }

    float inv = 1.f / l;
#pragma unroll
    for (int c = 0; c < 32; c++)
        O[qbase + (size_t)row * (NH * DH) + c * 4 + cg] = o[c] * inv;
}

// ---------------------------------------------------------------------------
// Launch
// ---------------------------------------------------------------------------
extern "C" void kernel_launch(void* const* d_in, const int* in_sizes, int n_in,
                              void* d_out, int out_size)
{
    const float* x     = (const float*)d_in[0];
    const float* freqs = (const float*)d_in[1];
    const float* wq    = (const float*)d_in[2];
    const float* wk    = (const float*)d_in[3];
    const float* wv    = (const float*)d_in[4];
    const float* wo    = (const float*)d_in[5];
    float* out = (float*)d_out;

    float *Qd, *Kd, *Vd, *Od;
    cudaGetSymbolAddress((void**)&Qd, g_Q);
    cudaGetSymbolAddress((void**)&Kd, g_K);
    cudaGetSymbolAddress((void**)&Vd, g_V);
    cudaGetSymbolAddress((void**)&Od, g_O);

    // QKV projections
    {
        dim3 gq(HID / 128, ROWS / 128);            // (16, 32)
        sgemm128<<<gq, 256>>>(x, wq, Qd, ROWS, NH * DH, HID);
        dim3 gk((NKV * DH) / 128, ROWS / 128);     // (4, 32)
        sgemm128<<<gk, 256>>>(x, wk, Kd, ROWS, NKV * DH, HID);
        sgemm128<<<gk, 256>>>(x, wv, Vd, ROWS, NKV * DH, HID);
    }

    // RoPE on Q and K
    {
        int total = ROWS * NH * (DH / 2) + ROWS * NKV * (DH / 2);
        rope_kernel<<<(total + 255) / 256, 256>>>(Qd, Kd, freqs);
    }

    // Attention
    {
        const int smem_bytes = (BQ * QPAD + BK * QPAD + BK * DH + BQ * PPAD) * 4;
        cudaFuncSetAttribute(attn_kernel,
                             cudaFuncAttributeMaxDynamicSharedMemorySize, smem_bytes);
        dim3 ga(S_LEN / BQ, B_SZ * NH);            // (32, 32)
        attn_kernel<<<ga, 256, smem_bytes>>>(Qd, Kd, Vd, Od);
    }

    // Output projection
    {
        dim3 go(HID / 128, ROWS / 128);
        sgemm128<<<go, 256>>>(Od, wo, out, ROWS, HID, NH * DH);
    }
}

// round 3
// speedup vs baseline: 1.2537x; 1.2537x over previous
#include <cuda_runtime.h>
#include <cuda_bf16.h>
#include <math.h>
#include <stdint.h>

// Problem constants
#define B_SZ   2
#define S_LEN  2048
#define HID    2048
#define NH     16
#define NKV    4
#define DH     128
#define GROUPS (NH / NKV)
#define ROWS   (B_SZ * S_LEN)        // 4096

// Scratch (static device globals; allocation-free)
__device__ float g_Q[ROWS * NH * DH];    // 4096 x 2048
__device__ float g_K[ROWS * NKV * DH];   // 4096 x 512
__device__ float g_V[ROWS * NKV * DH];   // 4096 x 512
__device__ float g_O[ROWS * NH * DH];    // 4096 x 2048

// ---------------------------------------------------------------------------
// TF32 helpers
// ---------------------------------------------------------------------------
__device__ __forceinline__ uint32_t f2tf32(float f) {
    uint32_t u;
    asm("cvt.rna.tf32.f32 %0, %1;" : "=r"(u) : "f"(f));
    return u;
}

__device__ __forceinline__ void mma_tf32(float* d, const uint32_t* a, const uint32_t* b) {
    asm volatile(
        "mma.sync.aligned.m16n8k8.row.col.f32.tf32.tf32.f32 "
        "{%0,%1,%2,%3}, {%4,%5,%6,%7}, {%8,%9}, {%0,%1,%2,%3};\n"
        : "+f"(d[0]), "+f"(d[1]), "+f"(d[2]), "+f"(d[3])
        : "r"(a[0]), "r"(a[1]), "r"(a[2]), "r"(a[3]),
          "r"(b[0]), "r"(b[1]));
}

// ---------------------------------------------------------------------------
// TF32 tensor-core GEMM: C[M,N] = A[M,K] @ B[K,N], row-major fp32 in/out.
// 128x128 block tile, BK=32, 128 threads (4 warps, 64x64 warp tiles).
// Requires M%128==0, N%128==0, K%32==0 (true for all our shapes).
// Smem strides (36 / 136) make all fragment LDS bank-conflict-free.
// ---------------------------------------------------------------------------
#define GBM 128
#define GBN 128
#define GBK 32
#define ASTR 36
#define BSTR 136

__global__ __launch_bounds__(128) void gemm_tf32(
    const float* __restrict__ A, const float* __restrict__ B,
    float* __restrict__ C, int M, int N, int K)
{
    __shared__ uint32_t As[GBM][ASTR];   // [m][k]  (pad->36)
    __shared__ uint32_t Bs[GBK][BSTR];   // [k][n]  (pad->136)

    const int tid  = threadIdx.x;
    const int lane = tid & 31;
    const int w    = tid >> 5;          // 0..3
    const int wm   = (w >> 1) * 64;
    const int wn   = (w & 1) * 64;
    const int bm   = blockIdx.y * GBM;
    const int bn   = blockIdx.x * GBN;

    float acc[4][8][4] = {};

    for (int k0 = 0; k0 < K; k0 += GBK) {
        // Stage A tile (128x32) -> tf32 smem
#pragma unroll
        for (int i = 0; i < 8; i++) {
            int t = tid + i * 128;
            int r = t >> 3;            // 0..127
            int c = (t & 7) * 4;       // 0..28
            float4 v = *(const float4*)(A + (size_t)(bm + r) * K + k0 + c);
            uint4 u;
            u.x = f2tf32(v.x); u.y = f2tf32(v.y);
            u.z = f2tf32(v.z); u.w = f2tf32(v.w);
            *(uint4*)&As[r][c] = u;
        }
        // Stage B tile (32x128) -> tf32 smem
#pragma unroll
        for (int i = 0; i < 8; i++) {
            int t = tid + i * 128;
            int r = t >> 5;            // 0..31
            int c = (t & 31) * 4;      // 0..124
            float4 v = *(const float4*)(B + (size_t)(k0 + r) * N + bn + c);
            uint4 u;
            u.x = f2tf32(v.x); u.y = f2tf32(v.y);
            u.z = f2tf32(v.z); u.w = f2tf32(v.w);
            *(uint4*)&Bs[r][c] = u;
        }
        __syncthreads();

#pragma unroll
        for (int kk = 0; kk < GBK; kk += 8) {
            uint32_t af[4][4], bf[8][2];
#pragma unroll
            for (int mi = 0; mi < 4; mi++) {
                int r = wm + mi * 16 + (lane >> 2);
                int c = kk + (lane & 3);
                af[mi][0] = As[r][c];
                af[mi][1] = As[r + 8][c];
                af[mi][2] = As[r][c + 4];
                af[mi][3] = As[r + 8][c + 4];
            }
#pragma unroll
            for (int ni = 0; ni < 8; ni++) {
                int c = wn + ni * 8 + (lane >> 2);
                int r = kk + (lane & 3);
                bf[ni][0] = Bs[r][c];
                bf[ni][1] = Bs[r + 4][c];
            }
#pragma unroll
            for (int mi = 0; mi < 4; mi++)
#pragma unroll
                for (int ni = 0; ni < 8; ni++)
                    mma_tf32(acc[mi][ni], af[mi], bf[ni]);
        }
        __syncthreads();
    }

    // Epilogue: fragment layout c0,c1 at (row, 2c),(row, 2c+1); c2,c3 at row+8
#pragma unroll
    for (int mi = 0; mi < 4; mi++) {
        int r0 = bm + wm + mi * 16 + (lane >> 2);
#pragma unroll
        for (int ni = 0; ni < 8; ni++) {
            int c = bn + wn + ni * 8 + 2 * (lane & 3);
            *(float2*)(C + (size_t)r0 * N + c) =
                make_float2(acc[mi][ni][0], acc[mi][ni][1]);
            *(float2*)(C + (size_t)(r0 + 8) * N + c) =
                make_float2(acc[mi][ni][2], acc[mi][ni][3]);
        }
    }
}

// ---------------------------------------------------------------------------
// RoPE (interleaved pairs) applied in-place to g_Q and g_K.
// freqs layout: [S, D/2, 2] => freqs[s*128 + 2*i] = cos, +1 = sin
// ---------------------------------------------------------------------------
__global__ __launch_bounds__(256) void rope_kernel(
    float* __restrict__ Q, float* __restrict__ Kt,
    const float* __restrict__ freqs)
{
    const int QP = ROWS * NH * (DH / 2);    // 4,194,304
    const int KP = ROWS * NKV * (DH / 2);   // 1,048,576
    int idx = blockIdx.x * blockDim.x + threadIdx.x;
    if (idx < QP) {
        int i   = idx & 63;
        int h   = (idx >> 6) & (NH - 1);
        int row = idx >> 10;
        int s   = row & (S_LEN - 1);
        float c  = freqs[s * 128 + 2 * i];
        float sn = freqs[s * 128 + 2 * i + 1];
        float* p = Q + (size_t)row * (NH * DH) + h * DH + 2 * i;
        float xr = p[0], xi = p[1];
        p[0] = xr * c - xi * sn;
        p[1] = xr * sn + xi * c;
    } else if (idx < QP + KP) {
        int j   = idx - QP;
        int i   = j & 63;
        int h   = (j >> 6) & (NKV - 1);
        int row = j >> 8;
        int s   = row & (S_LEN - 1);
        float c  = freqs[s * 128 + 2 * i];
        float sn = freqs[s * 128 + 2 * i + 1];
        float* p = Kt + (size_t)row * (NKV * DH) + h * DH + 2 * i;
        float xr = p[0], xi = p[1];
        p[0] = xr * c - xi * sn;
        p[1] = xr * sn + xi * c;
    }
}

// ---------------------------------------------------------------------------
// Flash attention (fp32, causal, GQA). One block = 64 queries of one (b,h).
// ---------------------------------------------------------------------------
#define BQ 64
#define BK 64
#define QPAD 132
#define PPAD 65

__global__ __launch_bounds__(256) void attn_kernel(
    const float* __restrict__ Q, const float* __restrict__ K,
    const float* __restrict__ V, float* __restrict__ O)
{
    extern __shared__ float sm[];
    float* Qs = sm;                       // 64*132
    float* Ks = Qs + BQ * QPAD;           // 64*132
    float* Vs = Ks + BK * QPAD;           // 64*128
    float* Ps = Vs + BK * DH;             // 64*65

    const int qt  = blockIdx.x;
    const int bh  = blockIdx.y;
    const int b   = bh / NH;
    const int h   = bh % NH;
    const int kvh = h / GROUPS;
    const int tid = threadIdx.x;
    const int row = tid >> 2;
    const int cg  = tid & 3;

    const float scale = 0.08838834764831845f;  // 1/sqrt(128)

    const size_t qbase = ((size_t)(b * S_LEN + qt * BQ)) * (NH * DH) + h * DH;
    for (int t = tid; t < BQ * DH / 4; t += 256) {
        int r  = t >> 5;
        int c4 = (t & 31) * 4;
        float4 v = *(const float4*)(Q + qbase + (size_t)r * (NH * DH) + c4);
        v.x *= scale; v.y *= scale; v.z *= scale; v.w *= scale;
        *(float4*)&Qs[r * QPAD + c4] = v;
    }

    float m = -INFINITY, l = 0.f;
    float o[32];
#pragma unroll
    for (int c = 0; c < 32; c++) o[c] = 0.f;

    const size_t kbase = ((size_t)(b * S_LEN)) * (NKV * DH) + kvh * DH;
    const int q_global = qt * BQ + row;

    for (int kt = 0; kt <= qt; ++kt) {
        __syncthreads();
        for (int t = tid; t < BK * DH / 4; t += 256) {
            int r  = t >> 5;
            int c4 = (t & 31) * 4;
            size_t g = kbase + (size_t)(kt * BK + r) * (NKV * DH) + c4;
            *(float4*)&Ks[r * QPAD + c4] = *(const float4*)(K + g);
            *(float4*)&Vs[r * DH + c4]   = *(const float4*)(V + g);
        }
        __syncthreads();

        float s[16];
#pragma unroll
        for (int jj = 0; jj < 16; jj++) s[jj] = 0.f;
        for (int k = 0; k < DH; k++) {
            float qv = Qs[row * QPAD + k];
#pragma unroll
            for (int jj = 0; jj < 16; jj++)
                s[jj] += qv * Ks[(jj * 4 + cg) * QPAD + k];
        }

        if (kt == qt) {
#pragma unroll
            for (int jj = 0; jj < 16; jj++) {
                int jg = kt * BK + jj * 4 + cg;
                if (jg > q_global) s[jj] = -INFINITY;
            }
        }

        float tmax = s[0];
#pragma unroll
        for (int jj = 1; jj < 16; jj++) tmax = fmaxf(tmax, s[jj]);
        tmax = fmaxf(tmax, __shfl_xor_sync(0xffffffffu, tmax, 1));
        tmax = fmaxf(tmax, __shfl_xor_sync(0xffffffffu, tmax, 2));
        float mnew = fmaxf(m, tmax);
        float corr = expf(m - mnew);

        float psum = 0.f;
#pragma unroll
        for (int jj = 0; jj < 16; jj++) {
            float p = expf(s[jj] - mnew);
            s[jj] = p;
            psum += p;
        }
        psum += __shfl_xor_sync(0xffffffffu, psum, 1);
        psum += __shfl_xor_sync(0xffffffffu, psum, 2);
        l = l * corr + psum;
        m = mnew;
#pragma unroll
        for (int c = 0; c < 32; c++) o[c] *= corr;

#pragma unroll
        for (int jj = 0; jj < 16; jj++) Ps[row * PPAD + jj * 4 + cg] = s[jj];
        __syncwarp();

        for (int j = 0; j < BK; j++) {
            float pv = Ps[row * PPAD + j];
#pragma unroll
            for (int c = 0; c < 32; c++)
                o[c] += pv * Vs[j * DH + c * 4 + cg];
        }
    }

    float inv = 1.f / l;
#pragma unroll
    for (int c = 0; c < 32; c++)
        O[qbase + (size_t)row * (NH * DH) + c * 4 + cg] = o[c] * inv;
}

// ---------------------------------------------------------------------------
// Launch
// ---------------------------------------------------------------------------
extern "C" void kernel_launch(void* const* d_in, const int* in_sizes, int n_in,
                              void* d_out, int out_size)
{
    const float* x     = (const float*)d_in[0];
    const float* freqs = (const float*)d_in[1];
    const float* wq    = (const float*)d_in[2];
    const float* wk    = (const float*)d_in[3];
    const float* wv    = (const float*)d_in[4];
    const float* wo    = (const float*)d_in[5];
    float* out = (float*)d_out;

    float *Qd, *Kd, *Vd, *Od;
    cudaGetSymbolAddress((void**)&Qd, g_Q);
    cudaGetSymbolAddress((void**)&Kd, g_K);
    cudaGetSymbolAddress((void**)&Vd, g_V);
    cudaGetSymbolAddress((void**)&Od, g_O);

    // QKV projections (tf32 tensor cores)
    {
        dim3 gq(HID / GBN, ROWS / GBM);            // (16, 32)
        gemm_tf32<<<gq, 128>>>(x, wq, Qd, ROWS, NH * DH, HID);
        dim3 gk((NKV * DH) / GBN, ROWS / GBM);     // (4, 32)
        gemm_tf32<<<gk, 128>>>(x, wk, Kd, ROWS, NKV * DH, HID);
        gemm_tf32<<<gk, 128>>>(x, wv, Vd, ROWS, NKV * DH, HID);
    }

    // RoPE on Q and K
    {
        int total = ROWS * NH * (DH / 2) + ROWS * NKV * (DH / 2);
        rope_kernel<<<(total + 255) / 256, 256>>>(Qd, Kd, freqs);
    }

    // Attention
    {
        const int smem_bytes = (BQ * QPAD + BK * QPAD + BK * DH + BQ * PPAD) * 4;
        cudaFuncSetAttribute(attn_kernel,
                             cudaFuncAttributeMaxDynamicSharedMemorySize, smem_bytes);
        dim3 ga(S_LEN / BQ, B_SZ * NH);            // (32, 32)
        attn_kernel<<<ga, 256, smem_bytes>>>(Qd, Kd, Vd, Od);
    }

    // Output projection (tf32 tensor cores)
    {
        dim3 go(HID / GBN, ROWS / GBM);
        gemm_tf32<<<go, 128>>>(Od, wo, out, ROWS, HID, NH * DH);
    }
}

// round 4
// speedup vs baseline: 3.0119x; 2.4025x over previous
#include <cuda_runtime.h>
#include <math.h>
#include <stdint.h>

// Problem constants
#define B_SZ   2
#define S_LEN  2048
#define HID    2048
#define NH     16
#define NKV    4
#define DH     128
#define GROUPS (NH / NKV)
#define ROWS   (B_SZ * S_LEN)        // 4096

// Scratch
__device__ float g_Q[ROWS * NH * DH];
__device__ float g_K[ROWS * NKV * DH];
__device__ float g_V[ROWS * NKV * DH];
__device__ float g_O[ROWS * NH * DH];

// ---------------------------------------------------------------------------
// Helpers
// ---------------------------------------------------------------------------
__device__ __forceinline__ uint32_t f2tf32(float f) {
    uint32_t u;
    asm("cvt.rna.tf32.f32 %0, %1;" : "=r"(u) : "f"(f));
    return u;
}

__device__ __forceinline__ void mma_tf32(float* d, const uint32_t* a, const uint32_t* b) {
    asm volatile(
        "mma.sync.aligned.m16n8k8.row.col.f32.tf32.tf32.f32 "
        "{%0,%1,%2,%3}, {%4,%5,%6,%7}, {%8,%9}, {%0,%1,%2,%3};\n"
        : "+f"(d[0]), "+f"(d[1]), "+f"(d[2]), "+f"(d[3])
        : "r"(a[0]), "r"(a[1]), "r"(a[2]), "r"(a[3]),
          "r"(b[0]), "r"(b[1]));
}

__device__ __forceinline__ uint32_t smem_u32(const void* p) {
    return (uint32_t)__cvta_generic_to_shared(p);
}

#define CP16(dst, src) asm volatile("cp.async.cg.shared.global [%0], [%1], 16;" :: "r"(dst), "l"(src))
#define CP_COMMIT()    asm volatile("cp.async.commit_group;")
#define CP_WAIT(n)     asm volatile("cp.async.wait_group %0;" :: "n"(n))

// ---------------------------------------------------------------------------
// Pipelined TF32 GEMM: C[M,N] = A[M,K] @ B[K,N], fp32 in/out.
// 128x128x32 tiles, 256 threads (8 warps, 32x64 warp tiles), 3-stage cp.async.
// ---------------------------------------------------------------------------
#define GBM 128
#define GBN 128
#define GBK 32
#define ASTR 36     // == 4 mod 32 -> A-style fragment loads conflict-free
#define BSTR 136    // == 8 mod 32 -> B-style fragment loads conflict-free
#define STAGES 3
#define A_STAGE (GBM * ASTR)
#define B_STAGE (GBK * BSTR)

__global__ __launch_bounds__(256) void gemm_tf32(
    const float* __restrict__ A, const float* __restrict__ B,
    float* __restrict__ C, int M, int N, int K)
{
    extern __shared__ float sh[];
    float* As = sh;                       // [STAGES][128][ASTR]
    float* Bs = sh + STAGES * A_STAGE;    // [STAGES][32][BSTR]

    const int tid  = threadIdx.x;
    const int lane = tid & 31;
    const int w    = tid >> 5;            // 0..7
    const int wm   = (w >> 1) * 32;
    const int wn   = (w & 1) * 64;
    const int bm   = blockIdx.y * GBM;
    const int bn   = blockIdx.x * GBN;

    const int KT = K / GBK;

    auto issue = [&](int buf, int k0) {
        float* as = As + buf * A_STAGE;
        float* bs = Bs + buf * B_STAGE;
#pragma unroll
        for (int i = 0; i < 4; i++) {
            int id = tid + i * 256;
            int r = id >> 3, c = (id & 7) * 4;
            CP16(smem_u32(as + r * ASTR + c), A + (size_t)(bm + r) * K + k0 + c);
        }
#pragma unroll
        for (int i = 0; i < 4; i++) {
            int id = tid + i * 256;
            int r = id >> 5, c = (id & 31) * 4;
            CP16(smem_u32(bs + r * BSTR + c), B + (size_t)(k0 + r) * N + bn + c);
        }
    };

    for (int s = 0; s < STAGES - 1; s++) { issue(s, s * GBK); CP_COMMIT(); }

    float acc[2][8][4] = {};

    for (int kt = 0; kt < KT; kt++) {
        CP_WAIT(STAGES - 2);
        __syncthreads();

        int nk = kt + STAGES - 1;
        if (nk < KT) issue(nk % STAGES, nk * GBK);
        CP_COMMIT();

        const float* as = As + (kt % STAGES) * A_STAGE;
        const float* bs = Bs + (kt % STAGES) * B_STAGE;

#pragma unroll
        for (int kk = 0; kk < GBK; kk += 8) {
            uint32_t af[2][4], bf[8][2];
#pragma unroll
            for (int mi = 0; mi < 2; mi++) {
                int r = wm + mi * 16 + (lane >> 2);
                int c = kk + (lane & 3);
                af[mi][0] = f2tf32(as[r * ASTR + c]);
                af[mi][1] = f2tf32(as[(r + 8) * ASTR + c]);
                af[mi][2] = f2tf32(as[r * ASTR + c + 4]);
                af[mi][3] = f2tf32(as[(r + 8) * ASTR + c + 4]);
            }
#pragma unroll
            for (int ni = 0; ni < 8; ni++) {
                int cc = wn + ni * 8 + (lane >> 2);
                int rr = kk + (lane & 3);
                bf[ni][0] = f2tf32(bs[rr * BSTR + cc]);
                bf[ni][1] = f2tf32(bs[(rr + 4) * BSTR + cc]);
            }
#pragma unroll
            for (int mi = 0; mi < 2; mi++)
#pragma unroll
                for (int ni = 0; ni < 8; ni++)
                    mma_tf32(acc[mi][ni], af[mi], bf[ni]);
        }
    }

#pragma unroll
    for (int mi = 0; mi < 2; mi++) {
        int r0 = bm + wm + mi * 16 + (lane >> 2);
#pragma unroll
        for (int ni = 0; ni < 8; ni++) {
            int c = bn + wn + ni * 8 + 2 * (lane & 3);
            *(float2*)(C + (size_t)r0 * N + c) =
                make_float2(acc[mi][ni][0], acc[mi][ni][1]);
            *(float2*)(C + (size_t)(r0 + 8) * N + c) =
                make_float2(acc[mi][ni][2], acc[mi][ni][3]);
        }
    }
}

// ---------------------------------------------------------------------------
// RoPE (interleaved pairs), in-place on Q and K.
// ---------------------------------------------------------------------------
__global__ __launch_bounds__(256) void rope_kernel(
    float* __restrict__ Q, float* __restrict__ Kt,
    const float* __restrict__ freqs)
{
    const int QP = ROWS * NH * (DH / 2);
    const int KP = ROWS * NKV * (DH / 2);
    int idx = blockIdx.x * blockDim.x + threadIdx.x;
    if (idx < QP) {
        int i   = idx & 63;
        int h   = (idx >> 6) & (NH - 1);
        int row = idx >> 10;
        int s   = row & (S_LEN - 1);
        float c  = freqs[s * 128 + 2 * i];
        float sn = freqs[s * 128 + 2 * i + 1];
        float* p = Q + (size_t)row * (NH * DH) + h * DH + 2 * i;
        float xr = p[0], xi = p[1];
        p[0] = xr * c - xi * sn;
        p[1] = xr * sn + xi * c;
    } else if (idx < QP + KP) {
        int j   = idx - QP;
        int i   = j & 63;
        int h   = (j >> 6) & (NKV - 1);
        int row = j >> 8;
        int s   = row & (S_LEN - 1);
        float c  = freqs[s * 128 + 2 * i];
        float sn = freqs[s * 128 + 2 * i + 1];
        float* p = Kt + (size_t)row * (NKV * DH) + h * DH + 2 * i;
        float xr = p[0], xi = p[1];
        p[0] = xr * c - xi * sn;
        p[1] = xr * sn + xi * c;
    }
}

// ---------------------------------------------------------------------------
// TF32 tensor-core flash attention (causal, GQA).
// One block: 128 queries of one (b,h). 256 threads = 8 warps x 16 q-rows.
// Key tiles of 32, 2-stage cp.async K/V pipeline, online softmax in regs.
// ---------------------------------------------------------------------------
#define AQ 128
#define AK 32
#define QSTR 132
#define KSTR 132
#define VSTR 136
#define PSTR 36

__global__ __launch_bounds__(256) void attn_tc(
    const float* __restrict__ Q, const float* __restrict__ K,
    const float* __restrict__ V, float* __restrict__ O)
{
    extern __shared__ float sh[];
    float* Qs = sh;                         // 128*132
    float* Ks = Qs + AQ * QSTR;             // 2 * 32*132
    float* Vs = Ks + 2 * AK * KSTR;         // 2 * 32*136
    float* Ps = Vs + 2 * AK * VSTR;         // 128*36

    const int qt  = gridDim.x - 1 - blockIdx.x;   // heavy blocks first
    const int bh  = blockIdx.y;
    const int b   = bh >> 4;
    const int h   = bh & 15;
    const int kvh = h >> 2;                 // h / GROUPS
    const int tid = threadIdx.x;
    const int lane = tid & 31;
    const int w    = tid >> 5;

    const float scale = 0.08838834764831845f;  // 1/sqrt(128)

    const size_t qbase = ((size_t)(b * S_LEN + qt * AQ)) * (NH * DH) + h * DH;
    for (int t = tid; t < AQ * DH / 4; t += 256) {
        int r = t >> 5, c = (t & 31) * 4;
        float4 v = *(const float4*)(Q + qbase + (size_t)r * (NH * DH) + c);
        v.x *= scale; v.y *= scale; v.z *= scale; v.w *= scale;
        *(float4*)&Qs[r * QSTR + c] = v;
    }

    const size_t kvbase = ((size_t)(b * S_LEN)) * (NKV * DH) + kvh * DH;

    auto issueKV = [&](int buf, int kt) {
        float* ks = Ks + buf * AK * KSTR;
        float* vs = Vs + buf * AK * VSTR;
#pragma unroll
        for (int i = 0; i < 4; i++) {
            int id = tid + i * 256;
            int r = id >> 5, c = (id & 31) * 4;
            size_t g = kvbase + (size_t)(kt * AK + r) * (NKV * DH) + c;
            CP16(smem_u32(ks + r * KSTR + c), K + g);
            CP16(smem_u32(vs + r * VSTR + c), V + g);
        }
    };

    const int KT = 4 * qt + 4;
    issueKV(0, 0); CP_COMMIT();

    const int rA = w * 16 + (lane >> 2);     // row0 within tile (row1 = rA+8)
    const int q0 = qt * AQ + rA;
    const int q1 = q0 + 8;

    float m0 = -INFINITY, m1 = -INFINITY, l0 = 0.f, l1 = 0.f;
    float oacc[16][4] = {};

    for (int kt = 0; kt < KT; kt++) {
        __syncthreads();                     // prev tile fully consumed
        if (kt + 1 < KT) issueKV((kt + 1) & 1, kt + 1);
        CP_COMMIT();
        CP_WAIT(1);
        __syncthreads();

        const float* ks = Ks + (kt & 1) * AK * KSTR;
        const float* vs = Vs + (kt & 1) * AK * VSTR;

        // S = Q @ Ktile^T  (warp: 16 rows x 32 keys)
        float sacc[4][4] = {};
#pragma unroll
        for (int kk = 0; kk < DH; kk += 8) {
            uint32_t af[4], bf[4][2];
            int c = kk + (lane & 3);
            af[0] = f2tf32(Qs[rA * QSTR + c]);
            af[1] = f2tf32(Qs[(rA + 8) * QSTR + c]);
            af[2] = f2tf32(Qs[rA * QSTR + c + 4]);
            af[3] = f2tf32(Qs[(rA + 8) * QSTR + c + 4]);
#pragma unroll
            for (int ni = 0; ni < 4; ni++) {
                int key = ni * 8 + (lane >> 2);
                bf[ni][0] = f2tf32(ks[key * KSTR + c]);
                bf[ni][1] = f2tf32(ks[key * KSTR + c + 4]);
            }
#pragma unroll
            for (int ni = 0; ni < 4; ni++) mma_tf32(sacc[ni], af, bf[ni]);
        }

        // causal mask (only tiles touching/above the diagonal)
        if (kt >= 4 * qt) {
            int kb = kt * AK + 2 * (lane & 3);
#pragma unroll
            for (int ni = 0; ni < 4; ni++) {
                int kc = kb + ni * 8;
                if (kc     > q0) sacc[ni][0] = -INFINITY;
                if (kc + 1 > q0) sacc[ni][1] = -INFINITY;
                if (kc     > q1) sacc[ni][2] = -INFINITY;
                if (kc + 1 > q1) sacc[ni][3] = -INFINITY;
            }
        }

        // online softmax
        float t0 = -INFINITY, t1 = -INFINITY;
#pragma unroll
        for (int ni = 0; ni < 4; ni++) {
            t0 = fmaxf(t0, fmaxf(sacc[ni][0], sacc[ni][1]));
            t1 = fmaxf(t1, fmaxf(sacc[ni][2], sacc[ni][3]));
        }
        t0 = fmaxf(t0, __shfl_xor_sync(0xffffffffu, t0, 1));
        t0 = fmaxf(t0, __shfl_xor_sync(0xffffffffu, t0, 2));
        t1 = fmaxf(t1, __shfl_xor_sync(0xffffffffu, t1, 1));
        t1 = fmaxf(t1, __shfl_xor_sync(0xffffffffu, t1, 2));

        float n0 = fmaxf(m0, t0), n1 = fmaxf(m1, t1);
        float c0 = __expf(m0 - n0), c1 = __expf(m1 - n1);
        float s0 = 0.f, s1 = 0.f;
#pragma unroll
        for (int ni = 0; ni < 4; ni++) {
            sacc[ni][0] = __expf(sacc[ni][0] - n0);
            sacc[ni][1] = __expf(sacc[ni][1] - n0);
            sacc[ni][2] = __expf(sacc[ni][2] - n1);
            sacc[ni][3] = __expf(sacc[ni][3] - n1);
            s0 += sacc[ni][0] + sacc[ni][1];
            s1 += sacc[ni][2] + sacc[ni][3];
        }
        s0 += __shfl_xor_sync(0xffffffffu, s0, 1);
        s0 += __shfl_xor_sync(0xffffffffu, s0, 2);
        s1 += __shfl_xor_sync(0xffffffffu, s1, 1);
        s1 += __shfl_xor_sync(0xffffffffu, s1, 2);
        l0 = l0 * c0 + s0;  l1 = l1 * c1 + s1;
        m0 = n0;            m1 = n1;

#pragma unroll
        for (int ni = 0; ni < 16; ni++) {
            oacc[ni][0] *= c0; oacc[ni][1] *= c0;
            oacc[ni][2] *= c1; oacc[ni][3] *= c1;
        }

        // P -> smem (warp-private strip), then O += P @ V
#pragma unroll
        for (int ni = 0; ni < 4; ni++) {
            int c = ni * 8 + 2 * (lane & 3);
            Ps[rA * PSTR + c]           = sacc[ni][0];
            Ps[rA * PSTR + c + 1]       = sacc[ni][1];
            Ps[(rA + 8) * PSTR + c]     = sacc[ni][2];
            Ps[(rA + 8) * PSTR + c + 1] = sacc[ni][3];
        }
        __syncwarp();

#pragma unroll
        for (int kk = 0; kk < AK; kk += 8) {
            uint32_t af[4];
            int c = kk + (lane & 3);
            af[0] = f2tf32(Ps[rA * PSTR + c]);
            af[1] = f2tf32(Ps[(rA + 8) * PSTR + c]);
            af[2] = f2tf32(Ps[rA * PSTR + c + 4]);
            af[3] = f2tf32(Ps[(rA + 8) * PSTR + c + 4]);
#pragma unroll
            for (int ni = 0; ni < 16; ni++) {
                uint32_t bf[2];
                int d = ni * 8 + (lane >> 2);
                bf[0] = f2tf32(vs[(kk + (lane & 3)) * VSTR + d]);
                bf[1] = f2tf32(vs[(kk + 4 + (lane & 3)) * VSTR + d]);
                mma_tf32(oacc[ni], af, bf);
            }
        }
    }

    float i0 = 1.f / l0, i1 = 1.f / l1;
#pragma unroll
    for (int ni = 0; ni < 16; ni++) {
        int c = ni * 8 + 2 * (lane & 3);
        *(float2*)(O + qbase + (size_t)rA * (NH * DH) + c) =
            make_float2(oacc[ni][0] * i0, oacc[ni][1] * i0);
        *(float2*)(O + qbase + (size_t)(rA + 8) * (NH * DH) + c) =
            make_float2(oacc[ni][2] * i1, oacc[ni][3] * i1);
    }
}

// ---------------------------------------------------------------------------
// Launch
// ---------------------------------------------------------------------------
extern "C" void kernel_launch(void* const* d_in, const int* in_sizes, int n_in,
                              void* d_out, int out_size)
{
    const float* x     = (const float*)d_in[0];
    const float* freqs = (const float*)d_in[1];
    const float* wq    = (const float*)d_in[2];
    const float* wk    = (const float*)d_in[3];
    const float* wv    = (const float*)d_in[4];
    const float* wo    = (const float*)d_in[5];
    float* out = (float*)d_out;

    float *Qd, *Kd, *Vd, *Od;
    cudaGetSymbolAddress((void**)&Qd, g_Q);
    cudaGetSymbolAddress((void**)&Kd, g_K);
    cudaGetSymbolAddress((void**)&Vd, g_V);
    cudaGetSymbolAddress((void**)&Od, g_O);

    const int gemm_smem = (STAGES * A_STAGE + STAGES * B_STAGE) * 4;   // 107,520
    cudaFuncSetAttribute(gemm_tf32, cudaFuncAttributeMaxDynamicSharedMemorySize, gemm_smem);

    // QKV projections
    {
        dim3 gq(HID / GBN, ROWS / GBM);
        gemm_tf32<<<gq, 256, gemm_smem>>>(x, wq, Qd, ROWS, NH * DH, HID);
        dim3 gk((NKV * DH) / GBN, ROWS / GBM);
        gemm_tf32<<<gk, 256, gemm_smem>>>(x, wk, Kd, ROWS, NKV * DH, HID);
        gemm_tf32<<<gk, 256, gemm_smem>>>(x, wv, Vd, ROWS, NKV * DH, HID);
    }

    // RoPE
    {
        int total = ROWS * NH * (DH / 2) + ROWS * NKV * (DH / 2);
        rope_kernel<<<(total + 255) / 256, 256>>>(Qd, Kd, freqs);
    }

    // Attention (tensor cores)
    {
        const int attn_smem = (AQ * QSTR + 2 * AK * KSTR + 2 * AK * VSTR + AQ * PSTR) * 4;  // 154,624
        cudaFuncSetAttribute(attn_tc, cudaFuncAttributeMaxDynamicSharedMemorySize, attn_smem);
        dim3 ga(S_LEN / AQ, B_SZ * NH);    // (16, 32)
        attn_tc<<<ga, 256, attn_smem>>>(Qd, Kd, Vd, Od);
    }

    // Output projection
    {
        dim3 go(HID / GBN, ROWS / GBM);
        gemm_tf32<<<go, 256, gemm_smem>>>(Od, wo, out, ROWS, HID, NH * DH);
    }
}

// round 5
// speedup vs baseline: 5.5038x; 1.8273x over previous
#include <cuda_runtime.h>
#include <math.h>
#include <stdint.h>

// Problem constants
#define B_SZ   2
#define S_LEN  2048
#define HID    2048
#define NH     16
#define NKV    4
#define DH     128
#define GROUPS (NH / NKV)
#define ROWS   (B_SZ * S_LEN)        // 4096

// Scratch
__device__ float g_Q[ROWS * NH * DH];
__device__ float g_K[ROWS * NKV * DH];
__device__ float g_V[ROWS * NKV * DH];
__device__ float g_O[ROWS * NH * DH];
// Pre-rounded (rna->tf32) copies of inputs
__device__ float g_xr[ROWS * HID];
__device__ float g_wqr[HID * NH * DH];
__device__ float g_wkr[HID * NKV * DH];
__device__ float g_wvr[HID * NKV * DH];
__device__ float g_wor[NH * DH * HID];

// ---------------------------------------------------------------------------
// Helpers
// ---------------------------------------------------------------------------
__device__ __forceinline__ uint32_t f2tf32(float f) {
    uint32_t u;
    asm("cvt.rna.tf32.f32 %0, %1;" : "=r"(u) : "f"(f));
    return u;
}
__device__ __forceinline__ float rtf(float f) { return __uint_as_float(f2tf32(f)); }

__device__ __forceinline__ void mma_tf32(float* d, const uint32_t* a, const uint32_t* b) {
    asm volatile(
        "mma.sync.aligned.m16n8k8.row.col.f32.tf32.tf32.f32 "
        "{%0,%1,%2,%3}, {%4,%5,%6,%7}, {%8,%9}, {%0,%1,%2,%3};\n"
        : "+f"(d[0]), "+f"(d[1]), "+f"(d[2]), "+f"(d[3])
        : "r"(a[0]), "r"(a[1]), "r"(a[2]), "r"(a[3]),
          "r"(b[0]), "r"(b[1]));
}

__device__ __forceinline__ uint32_t smem_u32(const void* p) {
    return (uint32_t)__cvta_generic_to_shared(p);
}

#define CP16(dst, src) asm volatile("cp.async.cg.shared.global [%0], [%1], 16;" :: "r"(dst), "l"(src))
#define CP_COMMIT()    asm volatile("cp.async.commit_group;")
#define CP_WAIT(n)     asm volatile("cp.async.wait_group %0;" :: "n"(n))

// ---------------------------------------------------------------------------
// Elementwise rna->tf32 rounding pass (vectorized)
// ---------------------------------------------------------------------------
__global__ __launch_bounds__(256) void round_tf32(
    const float* __restrict__ in, float* __restrict__ out, int n4)
{
    int i = blockIdx.x * blockDim.x + threadIdx.x;
    if (i < n4) {
        float4 v = ((const float4*)in)[i];
        v.x = rtf(v.x); v.y = rtf(v.y); v.z = rtf(v.z); v.w = rtf(v.w);
        ((float4*)out)[i] = v;
    }
}

// ---------------------------------------------------------------------------
// Pipelined TF32 GEMM: C[M,N] = A[M,K] @ B[K,N]; A,B pre-rounded to tf32.
// 128x128x32 tiles, 128 threads (4 warps, 64x64 warp tiles), 3-stage cp.async.
// No cvt in the inner loop: smem bits feed HMMA directly.
// ---------------------------------------------------------------------------
#define GBM 128
#define GBN 128
#define GBK 32
#define ASTR 36     // == 4 mod 32 -> conflict-free A fragment loads
#define BSTR 136    // == 8 mod 32 -> conflict-free B fragment loads
#define STAGES 3
#define A_STAGE (GBM * ASTR)
#define B_STAGE (GBK * BSTR)

__global__ __launch_bounds__(128) void gemm_tf32(
    const float* __restrict__ A, const float* __restrict__ B,
    float* __restrict__ C, int M, int N, int K, int round_out)
{
    extern __shared__ float sh[];
    float* As = sh;
    float* Bs = sh + STAGES * A_STAGE;

    const int tid  = threadIdx.x;
    const int lane = tid & 31;
    const int w    = tid >> 5;            // 0..3
    const int wm   = (w >> 1) * 64;
    const int wn   = (w & 1) * 64;
    const int bm   = blockIdx.y * GBM;
    const int bn   = blockIdx.x * GBN;

    const int KT = K / GBK;

    auto issue = [&](int buf, int k0) {
        float* as = As + buf * A_STAGE;
        float* bs = Bs + buf * B_STAGE;
#pragma unroll
        for (int i = 0; i < 8; i++) {
            int id = tid + i * 128;
            int r = id >> 3, c = (id & 7) * 4;
            CP16(smem_u32(as + r * ASTR + c), A + (size_t)(bm + r) * K + k0 + c);
        }
#pragma unroll
        for (int i = 0; i < 8; i++) {
            int id = tid + i * 128;
            int r = id >> 5, c = (id & 31) * 4;
            CP16(smem_u32(bs + r * BSTR + c), B + (size_t)(k0 + r) * N + bn + c);
        }
    };

    for (int s = 0; s < STAGES - 1; s++) { issue(s, s * GBK); CP_COMMIT(); }

    float acc[4][8][4] = {};

    for (int kt = 0; kt < KT; kt++) {
        CP_WAIT(STAGES - 2);
        __syncthreads();

        int nk = kt + STAGES - 1;
        if (nk < KT) issue(nk % STAGES, nk * GBK);
        CP_COMMIT();

        const float* as = As + (kt % STAGES) * A_STAGE;
        const float* bs = Bs + (kt % STAGES) * B_STAGE;

#pragma unroll
        for (int kk = 0; kk < GBK; kk += 8) {
            uint32_t af[4][4], bf[8][2];
#pragma unroll
            for (int mi = 0; mi < 4; mi++) {
                int r = wm + mi * 16 + (lane >> 2);
                int c = kk + (lane & 3);
                af[mi][0] = __float_as_uint(as[r * ASTR + c]);
                af[mi][1] = __float_as_uint(as[(r + 8) * ASTR + c]);
                af[mi][2] = __float_as_uint(as[r * ASTR + c + 4]);
                af[mi][3] = __float_as_uint(as[(r + 8) * ASTR + c + 4]);
            }
#pragma unroll
            for (int ni = 0; ni < 8; ni++) {
                int cc = wn + ni * 8 + (lane >> 2);
                int rr = kk + (lane & 3);
                bf[ni][0] = __float_as_uint(bs[rr * BSTR + cc]);
                bf[ni][1] = __float_as_uint(bs[(rr + 4) * BSTR + cc]);
            }
#pragma unroll
            for (int mi = 0; mi < 4; mi++)
#pragma unroll
                for (int ni = 0; ni < 8; ni++)
                    mma_tf32(acc[mi][ni], af[mi], bf[ni]);
        }
    }

#pragma unroll
    for (int mi = 0; mi < 4; mi++) {
        int r0 = bm + wm + mi * 16 + (lane >> 2);
#pragma unroll
        for (int ni = 0; ni < 8; ni++) {
            int c = bn + wn + ni * 8 + 2 * (lane & 3);
            float v0 = acc[mi][ni][0], v1 = acc[mi][ni][1];
            float v2 = acc[mi][ni][2], v3 = acc[mi][ni][3];
            if (round_out) { v0 = rtf(v0); v1 = rtf(v1); v2 = rtf(v2); v3 = rtf(v3); }
            *(float2*)(C + (size_t)r0 * N + c)       = make_float2(v0, v1);
            *(float2*)(C + (size_t)(r0 + 8) * N + c) = make_float2(v2, v3);
        }
    }
}

// ---------------------------------------------------------------------------
// RoPE (interleaved pairs), in-place; outputs rna-rounded to tf32.
// ---------------------------------------------------------------------------
__global__ __launch_bounds__(256) void rope_kernel(
    float* __restrict__ Q, float* __restrict__ Kt,
    const float* __restrict__ freqs)
{
    const int QP = ROWS * NH * (DH / 2);
    const int KP = ROWS * NKV * (DH / 2);
    int idx = blockIdx.x * blockDim.x + threadIdx.x;
    if (idx < QP) {
        int i   = idx & 63;
        int h   = (idx >> 6) & (NH - 1);
        int row = idx >> 10;
        int s   = row & (S_LEN - 1);
        float c  = freqs[s * 128 + 2 * i];
        float sn = freqs[s * 128 + 2 * i + 1];
        float* p = Q + (size_t)row * (NH * DH) + h * DH + 2 * i;
        float xr = p[0], xi = p[1];
        p[0] = rtf(xr * c - xi * sn);
        p[1] = rtf(xr * sn + xi * c);
    } else if (idx < QP + KP) {
        int j   = idx - QP;
        int i   = j & 63;
        int h   = (j >> 6) & (NKV - 1);
        int row = j >> 8;
        int s   = row & (S_LEN - 1);
        float c  = freqs[s * 128 + 2 * i];
        float sn = freqs[s * 128 + 2 * i + 1];
        float* p = Kt + (size_t)row * (NKV * DH) + h * DH + 2 * i;
        float xr = p[0], xi = p[1];
        p[0] = rtf(xr * c - xi * sn);
        p[1] = rtf(xr * sn + xi * c);
    }
}

// ---------------------------------------------------------------------------
// TF32 tensor-core flash attention (causal, GQA).
// Q/K/V arrive tf32-pre-rounded -> no cvt in QK^T / V fragments.
// ---------------------------------------------------------------------------
#define AQ 128
#define AK 32
#define QSTR 132
#define KSTR 132
#define VSTR 136
#define PSTR 36

__global__ __launch_bounds__(256) void attn_tc(
    const float* __restrict__ Q, const float* __restrict__ K,
    const float* __restrict__ V, float* __restrict__ O)
{
    extern __shared__ float sh[];
    float* Qs = sh;                         // 128*132
    float* Ks = Qs + AQ * QSTR;             // 2 * 32*132
    float* Vs = Ks + 2 * AK * KSTR;         // 2 * 32*136
    float* Ps = Vs + 2 * AK * VSTR;         // 128*36

    const int qt  = gridDim.x - 1 - blockIdx.x;   // heavy blocks first
    const int bh  = blockIdx.y;
    const int b   = bh >> 4;
    const int h   = bh & 15;
    const int kvh = h >> 2;
    const int tid = threadIdx.x;
    const int lane = tid & 31;
    const int w    = tid >> 5;

    const float scale = 0.08838834764831845f;  // 1/sqrt(128)

    const size_t qbase = ((size_t)(b * S_LEN + qt * AQ)) * (NH * DH) + h * DH;
    for (int t = tid; t < AQ * DH / 4; t += 256) {
        int r = t >> 5, c = (t & 31) * 4;
        float4 v = *(const float4*)(Q + qbase + (size_t)r * (NH * DH) + c);
        v.x = rtf(v.x * scale); v.y = rtf(v.y * scale);
        v.z = rtf(v.z * scale); v.w = rtf(v.w * scale);
        *(float4*)&Qs[r * QSTR + c] = v;
    }

    const size_t kvbase = ((size_t)(b * S_LEN)) * (NKV * DH) + kvh * DH;

    auto issueKV = [&](int buf, int kt) {
        float* ks = Ks + buf * AK * KSTR;
        float* vs = Vs + buf * AK * VSTR;
#pragma unroll
        for (int i = 0; i < 4; i++) {
            int id = tid + i * 256;
            int r = id >> 5, c = (id & 31) * 4;
            size_t g = kvbase + (size_t)(kt * AK + r) * (NKV * DH) + c;
            CP16(smem_u32(ks + r * KSTR + c), K + g);
            CP16(smem_u32(vs + r * VSTR + c), V + g);
        }
    };

    const int KT = 4 * qt + 4;
    issueKV(0, 0); CP_COMMIT();

    const int rA = w * 16 + (lane >> 2);
    const int q0 = qt * AQ + rA;
    const int q1 = q0 + 8;

    float m0 = -INFINITY, m1 = -INFINITY, l0 = 0.f, l1 = 0.f;
    float oacc[16][4] = {};

    for (int kt = 0; kt < KT; kt++) {
        __syncthreads();
        if (kt + 1 < KT) issueKV((kt + 1) & 1, kt + 1);
        CP_COMMIT();
        CP_WAIT(1);
        __syncthreads();

        const float* ks = Ks + (kt & 1) * AK * KSTR;
        const float* vs = Vs + (kt & 1) * AK * VSTR;

        // S = Q @ Ktile^T
        float sacc[4][4] = {};
#pragma unroll
        for (int kk = 0; kk < DH; kk += 8) {
            uint32_t af[4], bf[4][2];
            int c = kk + (lane & 3);
            af[0] = __float_as_uint(Qs[rA * QSTR + c]);
            af[1] = __float_as_uint(Qs[(rA + 8) * QSTR + c]);
            af[2] = __float_as_uint(Qs[rA * QSTR + c + 4]);
            af[3] = __float_as_uint(Qs[(rA + 8) * QSTR + c + 4]);
#pragma unroll
            for (int ni = 0; ni < 4; ni++) {
                int key = ni * 8 + (lane >> 2);
                bf[ni][0] = __float_as_uint(ks[key * KSTR + c]);
                bf[ni][1] = __float_as_uint(ks[key * KSTR + c + 4]);
            }
#pragma unroll
            for (int ni = 0; ni < 4; ni++) mma_tf32(sacc[ni], af, bf[ni]);
        }

        if (kt >= 4 * qt) {
            int kb = kt * AK + 2 * (lane & 3);
#pragma unroll
            for (int ni = 0; ni < 4; ni++) {
                int kc = kb + ni * 8;
                if (kc     > q0) sacc[ni][0] = -INFINITY;
                if (kc + 1 > q0) sacc[ni][1] = -INFINITY;
                if (kc     > q1) sacc[ni][2] = -INFINITY;
                if (kc + 1 > q1) sacc[ni][3] = -INFINITY;
            }
        }

        float t0 = -INFINITY, t1 = -INFINITY;
#pragma unroll
        for (int ni = 0; ni < 4; ni++) {
            t0 = fmaxf(t0, fmaxf(sacc[ni][0], sacc[ni][1]));
            t1 = fmaxf(t1, fmaxf(sacc[ni][2], sacc[ni][3]));
        }
        t0 = fmaxf(t0, __shfl_xor_sync(0xffffffffu, t0, 1));
        t0 = fmaxf(t0, __shfl_xor_sync(0xffffffffu, t0, 2));
        t1 = fmaxf(t1, __shfl_xor_sync(0xffffffffu, t1, 1));
        t1 = fmaxf(t1, __shfl_xor_sync(0xffffffffu, t1, 2));

        float n0 = fmaxf(m0, t0), n1 = fmaxf(m1, t1);
        float c0 = __expf(m0 - n0), c1 = __expf(m1 - n1);
        float s0 = 0.f, s1 = 0.f;
#pragma unroll
        for (int ni = 0; ni < 4; ni++) {
            sacc[ni][0] = __expf(sacc[ni][0] - n0);
            sacc[ni][1] = __expf(sacc[ni][1] - n0);
            sacc[ni][2] = __expf(sacc[ni][2] - n1);
            sacc[ni][3] = __expf(sacc[ni][3] - n1);
            s0 += sacc[ni][0] + sacc[ni][1];
            s1 += sacc[ni][2] + sacc[ni][3];
        }
        s0 += __shfl_xor_sync(0xffffffffu, s0, 1);
        s0 += __shfl_xor_sync(0xffffffffu, s0, 2);
        s1 += __shfl_xor_sync(0xffffffffu, s1, 1);
        s1 += __shfl_xor_sync(0xffffffffu, s1, 2);
        l0 = l0 * c0 + s0;  l1 = l1 * c1 + s1;
        m0 = n0;            m1 = n1;

#pragma unroll
        for (int ni = 0; ni < 16; ni++) {
            oacc[ni][0] *= c0; oacc[ni][1] *= c0;
            oacc[ni][2] *= c1; oacc[ni][3] *= c1;
        }

#pragma unroll
        for (int ni = 0; ni < 4; ni++) {
            int c = ni * 8 + 2 * (lane & 3);
            Ps[rA * PSTR + c]           = sacc[ni][0];
            Ps[rA * PSTR + c + 1]       = sacc[ni][1];
            Ps[(rA + 8) * PSTR + c]     = sacc[ni][2];
            Ps[(rA + 8) * PSTR + c + 1] = sacc[ni][3];
        }
        __syncwarp();

#pragma unroll
        for (int kk = 0; kk < AK; kk += 8) {
            uint32_t af[4];
            int c = kk + (lane & 3);
            af[0] = f2tf32(Ps[rA * PSTR + c]);
            af[1] = f2tf32(Ps[(rA + 8) * PSTR + c]);
            af[2] = f2tf32(Ps[rA * PSTR + c + 4]);
            af[3] = f2tf32(Ps[(rA + 8) * PSTR + c + 4]);
#pragma unroll
            for (int ni = 0; ni < 16; ni++) {
                uint32_t bf[2];
                int d = ni * 8 + (lane >> 2);
                bf[0] = __float_as_uint(vs[(kk + (lane & 3)) * VSTR + d]);
                bf[1] = __float_as_uint(vs[(kk + 4 + (lane & 3)) * VSTR + d]);
                mma_tf32(oacc[ni], af, bf);
            }
        }
    }

    float i0 = 1.f / l0, i1 = 1.f / l1;
#pragma unroll
    for (int ni = 0; ni < 16; ni++) {
        int c = ni * 8 + 2 * (lane & 3);
        *(float2*)(O + qbase + (size_t)rA * (NH * DH) + c) =
            make_float2(rtf(oacc[ni][0] * i0), rtf(oacc[ni][1] * i0));
        *(float2*)(O + qbase + (size_t)(rA + 8) * (NH * DH) + c) =
            make_float2(rtf(oacc[ni][2] * i1), rtf(oacc[ni][3] * i1));
    }
}

// ---------------------------------------------------------------------------
// Launch
// ---------------------------------------------------------------------------
extern "C" void kernel_launch(void* const* d_in, const int* in_sizes, int n_in,
                              void* d_out, int out_size)
{
    const float* x     = (const float*)d_in[0];
    const float* freqs = (const float*)d_in[1];
    const float* wq    = (const float*)d_in[2];
    const float* wk    = (const float*)d_in[3];
    const float* wv    = (const float*)d_in[4];
    const float* wo    = (const float*)d_in[5];
    float* out = (float*)d_out;

    float *Qd, *Kd, *Vd, *Od, *xr, *wqr, *wkr, *wvr, *wor;
    cudaGetSymbolAddress((void**)&Qd, g_Q);
    cudaGetSymbolAddress((void**)&Kd, g_K);
    cudaGetSymbolAddress((void**)&Vd, g_V);
    cudaGetSymbolAddress((void**)&Od, g_O);
    cudaGetSymbolAddress((void**)&xr, g_xr);
    cudaGetSymbolAddress((void**)&wqr, g_wqr);
    cudaGetSymbolAddress((void**)&wkr, g_wkr);
    cudaGetSymbolAddress((void**)&wvr, g_wvr);
    cudaGetSymbolAddress((void**)&wor, g_wor);

    // Pre-round inputs to tf32 (rna)
    {
        int n;
        n = ROWS * HID / 4;         round_tf32<<<(n + 255) / 256, 256>>>(x,  xr,  n);
        n = HID * NH * DH / 4;      round_tf32<<<(n + 255) / 256, 256>>>(wq, wqr, n);
        n = HID * NKV * DH / 4;     round_tf32<<<(n + 255) / 256, 256>>>(wk, wkr, n);
        n = HID * NKV * DH / 4;     round_tf32<<<(n + 255) / 256, 256>>>(wv, wvr, n);
        n = NH * DH * HID / 4;      round_tf32<<<(n + 255) / 256, 256>>>(wo, wor, n);
    }

    const int gemm_smem = (STAGES * A_STAGE + STAGES * B_STAGE) * 4;   // 107,520
    cudaFuncSetAttribute(gemm_tf32, cudaFuncAttributeMaxDynamicSharedMemorySize, gemm_smem);

    // QKV projections (outputs rounded; rope re-rounds Q/K anyway)
    {
        dim3 gq(HID / GBN, ROWS / GBM);
        gemm_tf32<<<gq, 128, gemm_smem>>>(xr, wqr, Qd, ROWS, NH * DH, HID, 1);
        dim3 gk((NKV * DH) / GBN, ROWS / GBM);
        gemm_tf32<<<gk, 128, gemm_smem>>>(xr, wkr, Kd, ROWS, NKV * DH, HID, 1);
        gemm_tf32<<<gk, 128, gemm_smem>>>(xr, wvr, Vd, ROWS, NKV * DH, HID, 1);
    }

    // RoPE (rounds outputs)
    {
        int total = ROWS * NH * (DH / 2) + ROWS * NKV * (DH / 2);
        rope_kernel<<<(total + 255) / 256, 256>>>(Qd, Kd, freqs);
    }

    // Attention
    {
        const int attn_smem = (AQ * QSTR + 2 * AK * KSTR + 2 * AK * VSTR + AQ * PSTR) * 4;
        cudaFuncSetAttribute(attn_tc, cudaFuncAttributeMaxDynamicSharedMemorySize, attn_smem);
        dim3 ga(S_LEN / AQ, B_SZ * NH);
        attn_tc<<<ga, 256, attn_smem>>>(Qd, Kd, Vd, Od);
    }

    // Output projection (final: no rounding)
    {
        dim3 go(HID / GBN, ROWS / GBM);
        gemm_tf32<<<go, 128, gemm_smem>>>(Od, wor, out, ROWS, HID, NH * DH, 0);
    }
}

// round 7
// speedup vs baseline: 5.6121x; 1.0197x over previous
#include <cuda_runtime.h>
#include <math.h>
#include <stdint.h>

// Problem constants
#define B_SZ   2
#define S_LEN  2048
#define HID    2048
#define NH     16
#define NKV    4
#define DH     128
#define GROUPS (NH / NKV)
#define ROWS   (B_SZ * S_LEN)        // 4096

// Scratch
__device__ float g_Q[ROWS * NH * DH];
__device__ float g_K[ROWS * NKV * DH];
__device__ float g_V[ROWS * NKV * DH];
__device__ float g_O[ROWS * NH * DH];
__device__ float g_xp[ROWS * HID];             // permuted+rounded x   (A operand)
__device__ float g_Op[ROWS * NH * DH];         // permuted attention O (A operand)
__device__ float g_wqp[HID * NH * DH];         // permuted+rounded weights (B operand)
__device__ float g_wkp[HID * NKV * DH];
__device__ float g_wvp[HID * NKV * DH];
__device__ float g_wop[NH * DH * HID];

// ---------------------------------------------------------------------------
// Helpers
// ---------------------------------------------------------------------------
__device__ __forceinline__ uint32_t f2tf32(float f) {
    uint32_t u;
    asm("cvt.rna.tf32.f32 %0, %1;" : "=r"(u) : "f"(f));
    return u;
}
__device__ __forceinline__ float rtf(float f) { return __uint_as_float(f2tf32(f)); }

__device__ __forceinline__ void mma_tf32(float* d, const uint32_t* a, const uint32_t* b) {
    asm volatile(
        "mma.sync.aligned.m16n8k8.row.col.f32.tf32.tf32.f32 "
        "{%0,%1,%2,%3}, {%4,%5,%6,%7}, {%8,%9}, {%0,%1,%2,%3};\n"
        : "+f"(d[0]), "+f"(d[1]), "+f"(d[2]), "+f"(d[3])
        : "r"(a[0]), "r"(a[1]), "r"(a[2]), "r"(a[3]),
          "r"(b[0]), "r"(b[1]));
}

__device__ __forceinline__ uint32_t smem_u32(const void* p) {
    return (uint32_t)__cvta_generic_to_shared(p);
}

#define CP16(dst, src) asm volatile("cp.async.cg.shared.global [%0], [%1], 16;" :: "r"(dst), "l"(src))
#define CP_COMMIT()    asm volatile("cp.async.commit_group;")
#define CP_WAIT(n)     asm volatile("cp.async.wait_group %0;" :: "n"(n))

// ---------------------------------------------------------------------------
// Prep: permute into fragment-contiguous layouts (+ rna rounding).
// A_perm: [mt][kt][lane][4] : lane=(r8*4+c4), vals {(r,c),(r+8,c),(r,c+4),(r+8,c+4)}
// B_perm: [nt][kt][lane][2] : vals {(k,n),(k+4,n)}  from row-major W[K][N]
// ---------------------------------------------------------------------------
__global__ __launch_bounds__(256) void permuteA(
    const float* __restrict__ in, float* __restrict__ out, int M, int K)
{
    int id = blockIdx.x * 256 + threadIdx.x;
    int KT = K >> 3;
    int total = (M >> 4) * KT * 32;
    if (id >= total) return;
    int lane = id & 31;
    int kt   = (id >> 5) % KT;
    int mt   = (id >> 5) / KT;
    int r = mt * 16 + (lane >> 2);
    int c = kt * 8 + (lane & 3);
    const float* p = in + (size_t)r * K + c;
    float4 v;
    v.x = rtf(p[0]);
    v.y = rtf(p[(size_t)8 * K]);
    v.z = rtf(p[4]);
    v.w = rtf(p[(size_t)8 * K + 4]);
    ((float4*)out)[id] = v;
}

__global__ __launch_bounds__(256) void permuteB(
    const float* __restrict__ in, float* __restrict__ out, int K, int N)
{
    int id = blockIdx.x * 256 + threadIdx.x;
    int KT = K >> 3;
    int total = (N >> 3) * KT * 32;
    if (id >= total) return;
    int lane = id & 31;
    int kt   = (id >> 5) % KT;
    int nt   = (id >> 5) / KT;
    int k = kt * 8 + (lane & 3);
    int n = nt * 8 + (lane >> 2);
    float2 v;
    v.x = rtf(in[(size_t)k * N + n]);
    v.y = rtf(in[(size_t)(k + 4) * N + n]);
    ((float2*)out)[id] = v;
}

// ---------------------------------------------------------------------------
// Permuted-operand TF32 GEMM: C[M,N] = A @ B (A_perm, B_perm inputs).
// Block 128x256, 256 threads (8 warps, 64x64 warp tiles), K staged 32/stage,
// 3-stage cp.async. Fragment loads: A = 1x LDS.128, B = 1x LDS.64.
// ---------------------------------------------------------------------------
#define SA_BYTES 16384
#define SB_BYTES 32768
#define STG_BYTES (SA_BYTES + SB_BYTES)
#define NSTG 3
#define GSMEM (NSTG * STG_BYTES)        // 147,456

__global__ __launch_bounds__(256, 1) void gemm_p(
    const float* __restrict__ Ap, const float* __restrict__ Bp,
    float* __restrict__ C, int M, int N, int K, int round_out)
{
    extern __shared__ __align__(16) char smem[];

    const int tid  = threadIdx.x;
    const int lane = tid & 31;
    const int w    = tid >> 5;
    const int wm   = (w >> 2) * 64;       // 0 or 64
    const int wn   = (w & 3) * 64;        // 0..192
    const int bm   = blockIdx.y * 128;
    const int bn   = blockIdx.x * 256;

    const int KT8 = K >> 3;               // k-tiles of 8
    const int NKT = K >> 5;               // k-tiles of 32
    const int mt0 = bm >> 4;
    const int nt0 = bn >> 3;

    auto fill = [&](int buf, int ktile) {
        char* sA = smem + buf * STG_BYTES;
        char* sB = sA + SA_BYTES;
        int kt0 = ktile * 4;
#pragma unroll
        for (int i = 0; i < 4; i++) {
            int id = i * 256 + tid;                 // 0..1023
            size_t g = ((size_t)(mt0 + (id >> 7)) * KT8 + kt0) * 128 + (id & 127) * 4;
            CP16(smem_u32(sA + id * 16), Ap + g);
        }
#pragma unroll
        for (int i = 0; i < 8; i++) {
            int id = i * 256 + tid;                 // 0..2047
            size_t g = ((size_t)(nt0 + (id >> 6)) * KT8 + kt0) * 64 + (id & 63) * 4;
            CP16(smem_u32(sB + id * 16), Bp + g);
        }
    };

    fill(0, 0); CP_COMMIT();
    fill(1, 1); CP_COMMIT();

    float acc[4][8][4] = {};

    for (int t = 0; t < NKT; t++) {
        CP_WAIT(1);
        __syncthreads();
        if (t + 2 < NKT) fill((t + 2) % NSTG, t + 2);
        CP_COMMIT();

        const char* sA = smem + (t % NSTG) * STG_BYTES;
        const char* sB = sA + SA_BYTES;

#pragma unroll
        for (int kt = 0; kt < 4; kt++) {
            uint4 af[4];
            uint2 bf[8];
#pragma unroll
            for (int mi = 0; mi < 4; mi++) {
                int mtidx = (wm >> 4) + mi;
                af[mi] = *(const uint4*)(sA + (((mtidx * 4 + kt) * 32 + lane) << 4));
            }
#pragma unroll
            for (int ni = 0; ni < 8; ni++) {
                int ntidx = (wn >> 3) + ni;
                bf[ni] = *(const uint2*)(sB + (((ntidx * 4 + kt) * 32 + lane) << 3));
            }
#pragma unroll
            for (int mi = 0; mi < 4; mi++)
#pragma unroll
                for (int ni = 0; ni < 8; ni++)
                    mma_tf32(acc[mi][ni], (const uint32_t*)&af[mi], (const uint32_t*)&bf[ni]);
        }
    }

#pragma unroll
    for (int mi = 0; mi < 4; mi++) {
        int r0 = bm + wm + mi * 16 + (lane >> 2);
#pragma unroll
        for (int ni = 0; ni < 8; ni++) {
            int c = bn + wn + ni * 8 + 2 * (lane & 3);
            float v0 = acc[mi][ni][0], v1 = acc[mi][ni][1];
            float v2 = acc[mi][ni][2], v3 = acc[mi][ni][3];
            if (round_out) { v0 = rtf(v0); v1 = rtf(v1); v2 = rtf(v2); v3 = rtf(v3); }
            *(float2*)(C + (size_t)r0 * N + c)       = make_float2(v0, v1);
            *(float2*)(C + (size_t)(r0 + 8) * N + c) = make_float2(v2, v3);
        }
    }
}

// ---------------------------------------------------------------------------
// RoPE (interleaved pairs), in-place; outputs rna-rounded to tf32.
// ---------------------------------------------------------------------------
__global__ __launch_bounds__(256) void rope_kernel(
    float* __restrict__ Q, float* __restrict__ Kt,
    const float* __restrict__ freqs)
{
    const int QP = ROWS * NH * (DH / 2);
    const int KP = ROWS * NKV * (DH / 2);
    int idx = blockIdx.x * blockDim.x + threadIdx.x;
    if (idx < QP) {
        int i   = idx & 63;
        int h   = (idx >> 6) & (NH - 1);
        int row = idx >> 10;
        int s   = row & (S_LEN - 1);
        float c  = freqs[s * 128 + 2 * i];
        float sn = freqs[s * 128 + 2 * i + 1];
        float* p = Q + (size_t)row * (NH * DH) + h * DH + 2 * i;
        float xr = p[0], xi = p[1];
        p[0] = rtf(xr * c - xi * sn);
        p[1] = rtf(xr * sn + xi * c);
    } else if (idx < QP + KP) {
        int j   = idx - QP;
        int i   = j & 63;
        int h   = (j >> 6) & (NKV - 1);
        int row = j >> 8;
        int s   = row & (S_LEN - 1);
        float c  = freqs[s * 128 + 2 * i];
        float sn = freqs[s * 128 + 2 * i + 1];
        float* p = Kt + (size_t)row * (NKV * DH) + h * DH + 2 * i;
        float xr = p[0], xi = p[1];
        p[0] = rtf(xr * c - xi * sn);
        p[1] = rtf(xr * sn + xi * c);
    }
}

// ---------------------------------------------------------------------------
// TF32 legacy-mma flash attention (causal, GQA) — unchanged from R5 (passing).
// ---------------------------------------------------------------------------
#define AQ 128
#define AK 32
#define QSTR 132
#define KSTR 132
#define VSTR 136
#define PSTR 36

__global__ __launch_bounds__(256) void attn_tc(
    const float* __restrict__ Q, const float* __restrict__ K,
    const float* __restrict__ V, float* __restrict__ O)
{
    extern __shared__ float sh[];
    float* Qs = sh;
    float* Ks = Qs + AQ * QSTR;
    float* Vs = Ks + 2 * AK * KSTR;
    float* Ps = Vs + 2 * AK * VSTR;

    const int qt  = gridDim.x - 1 - blockIdx.x;
    const int bh  = blockIdx.y;
    const int b   = bh >> 4;
    const int h   = bh & 15;
    const int kvh = h >> 2;
    const int tid = threadIdx.x;
    const int lane = tid & 31;
    const int w    = tid >> 5;

    const float scale = 0.08838834764831845f;

    const size_t qbase = ((size_t)(b * S_LEN + qt * AQ)) * (NH * DH) + h * DH;
    for (int t = tid; t < AQ * DH / 4; t += 256) {
        int r = t >> 5, c = (t & 31) * 4;
        float4 v = *(const float4*)(Q + qbase + (size_t)r * (NH * DH) + c);
        v.x = rtf(v.x * scale); v.y = rtf(v.y * scale);
        v.z = rtf(v.z * scale); v.w = rtf(v.w * scale);
        *(float4*)&Qs[r * QSTR + c] = v;
    }

    const size_t kvbase = ((size_t)(b * S_LEN)) * (NKV * DH) + kvh * DH;

    auto issueKV = [&](int buf, int kt) {
        float* ks = Ks + buf * AK * KSTR;
        float* vs = Vs + buf * AK * VSTR;
#pragma unroll
        for (int i = 0; i < 4; i++) {
            int id = tid + i * 256;
            int r = id >> 5, c = (id & 31) * 4;
            size_t g = kvbase + (size_t)(kt * AK + r) * (NKV * DH) + c;
            CP16(smem_u32(ks + r * KSTR + c), K + g);
            CP16(smem_u32(vs + r * VSTR + c), V + g);
        }
    };

    const int KT = 4 * qt + 4;
    issueKV(0, 0); CP_COMMIT();

    const int rA = w * 16 + (lane >> 2);
    const int q0 = qt * AQ + rA;
    const int q1 = q0 + 8;

    float m0 = -INFINITY, m1 = -INFINITY, l0 = 0.f, l1 = 0.f;
    float oacc[16][4] = {};

    for (int kt = 0; kt < KT; kt++) {
        __syncthreads();
        if (kt + 1 < KT) issueKV((kt + 1) & 1, kt + 1);
        CP_COMMIT();
        CP_WAIT(1);
        __syncthreads();

        const float* ks = Ks + (kt & 1) * AK * KSTR;
        const float* vs = Vs + (kt & 1) * AK * VSTR;

        float sacc[4][4] = {};
#pragma unroll
        for (int kk = 0; kk < DH; kk += 8) {
            uint32_t af[4], bf[4][2];
            int c = kk + (lane & 3);
            af[0] = __float_as_uint(Qs[rA * QSTR + c]);
            af[1] = __float_as_uint(Qs[(rA + 8) * QSTR + c]);
            af[2] = __float_as_uint(Qs[rA * QSTR + c + 4]);
            af[3] = __float_as_uint(Qs[(rA + 8) * QSTR + c + 4]);
#pragma unroll
            for (int ni = 0; ni < 4; ni++) {
                int key = ni * 8 + (lane >> 2);
                bf[ni][0] = __float_as_uint(ks[key * KSTR + c]);
                bf[ni][1] = __float_as_uint(ks[key * KSTR + c + 4]);
            }
#pragma unroll
            for (int ni = 0; ni < 4; ni++) mma_tf32(sacc[ni], af, bf[ni]);
        }

        if (kt >= 4 * qt) {
            int kb = kt * AK + 2 * (lane & 3);
#pragma unroll
            for (int ni = 0; ni < 4; ni++) {
                int kc = kb + ni * 8;
                if (kc     > q0) sacc[ni][0] = -INFINITY;
                if (kc + 1 > q0) sacc[ni][1] = -INFINITY;
                if (kc     > q1) sacc[ni][2] = -INFINITY;
                if (kc + 1 > q1) sacc[ni][3] = -INFINITY;
            }
        }

        float t0 = -INFINITY, t1 = -INFINITY;
#pragma unroll
        for (int ni = 0; ni < 4; ni++) {
            t0 = fmaxf(t0, fmaxf(sacc[ni][0], sacc[ni][1]));
            t1 = fmaxf(t1, fmaxf(sacc[ni][2], sacc[ni][3]));
        }
        t0 = fmaxf(t0, __shfl_xor_sync(0xffffffffu, t0, 1));
        t0 = fmaxf(t0, __shfl_xor_sync(0xffffffffu, t0, 2));
        t1 = fmaxf(t1, __shfl_xor_sync(0xffffffffu, t1, 1));
        t1 = fmaxf(t1, __shfl_xor_sync(0xffffffffu, t1, 2));

        float n0 = fmaxf(m0, t0), n1 = fmaxf(m1, t1);
        float c0 = __expf(m0 - n0), c1 = __expf(m1 - n1);
        float s0 = 0.f, s1 = 0.f;
#pragma unroll
        for (int ni = 0; ni < 4; ni++) {
            sacc[ni][0] = __expf(sacc[ni][0] - n0);
            sacc[ni][1] = __expf(sacc[ni][1] - n0);
            sacc[ni][2] = __expf(sacc[ni][2] - n1);
            sacc[ni][3] = __expf(sacc[ni][3] - n1);
            s0 += sacc[ni][0] + sacc[ni][1];
            s1 += sacc[ni][2] + sacc[ni][3];
        }
        s0 += __shfl_xor_sync(0xffffffffu, s0, 1);
        s0 += __shfl_xor_sync(0xffffffffu, s0, 2);
        s1 += __shfl_xor_sync(0xffffffffu, s1, 1);
        s1 += __shfl_xor_sync(0xffffffffu, s1, 2);
        l0 = l0 * c0 + s0;  l1 = l1 * c1 + s1;
        m0 = n0;            m1 = n1;

#pragma unroll
        for (int ni = 0; ni < 16; ni++) {
            oacc[ni][0] *= c0; oacc[ni][1] *= c0;
            oacc[ni][2] *= c1; oacc[ni][3] *= c1;
        }

#pragma unroll
        for (int ni = 0; ni < 4; ni++) {
            int c = ni * 8 + 2 * (lane & 3);
            Ps[rA * PSTR + c]           = sacc[ni][0];
            Ps[rA * PSTR + c + 1]       = sacc[ni][1];
            Ps[(rA + 8) * PSTR + c]     = sacc[ni][2];
            Ps[(rA + 8) * PSTR + c + 1] = sacc[ni][3];
        }
        __syncwarp();

#pragma unroll
        for (int kk = 0; kk < AK; kk += 8) {
            uint32_t af[4];
            int c = kk + (lane & 3);
            af[0] = f2tf32(Ps[rA * PSTR + c]);
            af[1] = f2tf32(Ps[(rA + 8) * PSTR + c]);
            af[2] = f2tf32(Ps[rA * PSTR + c + 4]);
            af[3] = f2tf32(Ps[(rA + 8) * PSTR + c + 4]);
#pragma unroll
            for (int ni = 0; ni < 16; ni++) {
                uint32_t bf[2];
                int d = ni * 8 + (lane >> 2);
                bf[0] = __float_as_uint(vs[(kk + (lane & 3)) * VSTR + d]);
                bf[1] = __float_as_uint(vs[(kk + 4 + (lane & 3)) * VSTR + d]);
                mma_tf32(oacc[ni], af, bf);
            }
        }
    }

    float i0 = 1.f / l0, i1 = 1.f / l1;
#pragma unroll
    for (int ni = 0; ni < 16; ni++) {
        int c = ni * 8 + 2 * (lane & 3);
        *(float2*)(O + qbase + (size_t)rA * (NH * DH) + c) =
            make_float2(rtf(oacc[ni][0] * i0), rtf(oacc[ni][1] * i0));
        *(float2*)(O + qbase + (size_t)(rA + 8) * (NH * DH) + c) =
            make_float2(rtf(oacc[ni][2] * i1), rtf(oacc[ni][3] * i1));
    }
}

// ---------------------------------------------------------------------------
// Launch
// ---------------------------------------------------------------------------
extern "C" void kernel_launch(void* const* d_in, const int* in_sizes, int n_in,
                              void* d_out, int out_size)
{
    const float* x     = (const float*)d_in[0];
    const float* freqs = (const float*)d_in[1];
    const float* wq    = (const float*)d_in[2];
    const float* wk    = (const float*)d_in[3];
    const float* wv    = (const float*)d_in[4];
    const float* wo    = (const float*)d_in[5];
    float* out = (float*)d_out;

    float *Qd, *Kd, *Vd, *Od, *xp, *Op, *wqp, *wkp, *wvp, *wop;
    cudaGetSymbolAddress((void**)&Qd, g_Q);
    cudaGetSymbolAddress((void**)&Kd, g_K);
    cudaGetSymbolAddress((void**)&Vd, g_V);
    cudaGetSymbolAddress((void**)&Od, g_O);
    cudaGetSymbolAddress((void**)&xp, g_xp);
    cudaGetSymbolAddress((void**)&Op, g_Op);
    cudaGetSymbolAddress((void**)&wqp, g_wqp);
    cudaGetSymbolAddress((void**)&wkp, g_wkp);
    cudaGetSymbolAddress((void**)&wvp, g_wvp);
    cudaGetSymbolAddress((void**)&wop, g_wop);

    // Prep: permute + round
    {
        int n = (ROWS / 16) * (HID / 8) * 32;
        permuteA<<<(n + 255) / 256, 256>>>(x, xp, ROWS, HID);
        n = ((NH * DH) / 8) * (HID / 8) * 32;
        permuteB<<<(n + 255) / 256, 256>>>(wq, wqp, HID, NH * DH);
        n = ((NKV * DH) / 8) * (HID / 8) * 32;
        permuteB<<<(n + 255) / 256, 256>>>(wk, wkp, HID, NKV * DH);
        permuteB<<<(n + 255) / 256, 256>>>(wv, wvp, HID, NKV * DH);
        n = (HID / 8) * ((NH * DH) / 8) * 32;
        permuteB<<<(n + 255) / 256, 256>>>(wo, wop, NH * DH, HID);
    }

    cudaFuncSetAttribute(gemm_p, cudaFuncAttributeMaxDynamicSharedMemorySize, GSMEM);

    // QKV projections
    {
        dim3 gq(HID / 256, ROWS / 128);            // (8, 32)
        gemm_p<<<gq, 256, GSMEM>>>(xp, wqp, Qd, ROWS, NH * DH, HID, 1);
        dim3 gk((NKV * DH) / 256, ROWS / 128);     // (2, 32)
        gemm_p<<<gk, 256, GSMEM>>>(xp, wkp, Kd, ROWS, NKV * DH, HID, 1);
        gemm_p<<<gk, 256, GSMEM>>>(xp, wvp, Vd, ROWS, NKV * DH, HID, 1);
    }

    // RoPE
    {
        int total = ROWS * NH * (DH / 2) + ROWS * NKV * (DH / 2);
        rope_kernel<<<(total + 255) / 256, 256>>>(Qd, Kd, freqs);
    }

    // Attention
    {
        const int attn_smem = (AQ * QSTR + 2 * AK * KSTR + 2 * AK * VSTR + AQ * PSTR) * 4;
        cudaFuncSetAttribute(attn_tc, cudaFuncAttributeMaxDynamicSharedMemorySize, attn_smem);
        dim3 ga(S_LEN / AQ, B_SZ * NH);
        attn_tc<<<ga, 256, attn_smem>>>(Qd, Kd, Vd, Od);
    }

    // Permute attention output for the O projection, then final GEMM
    {
        int n = (ROWS / 16) * ((NH * DH) / 8) * 32;
        permuteA<<<(n + 255) / 256, 256>>>(Od, Op, ROWS, NH * DH);
        dim3 go(HID / 256, ROWS / 128);
        gemm_p<<<go, 256, GSMEM>>>(Op, wop, out, ROWS, HID, NH * DH, 0);
    }
}

// round 9
// speedup vs baseline: 7.8460x; 1.3981x over previous
#include <cuda_runtime.h>
#include <cuda_fp16.h>
#include <math.h>
#include <stdint.h>

// Problem constants
#define B_SZ   2
#define S_LEN  2048
#define HID    2048
#define NH     16
#define NKV    4
#define DH     128
#define GROUPS (NH / NKV)
#define ROWS   (B_SZ * S_LEN)        // 4096

// Scratch
__device__ float g_Q[ROWS * NH * DH];
__device__ float g_K[ROWS * NKV * DH];
__device__ float g_V[ROWS * NKV * DH];
__device__ float g_O[ROWS * NH * DH];
__device__ uint32_t g_xp4[(ROWS / 16) * (HID / 16) * 32 * 4];        // x A-frag (fp16)
__device__ uint32_t g_Op4[(ROWS / 16) * ((NH * DH) / 16) * 32 * 4];  // attn-O A-frag
__device__ uint32_t g_wqp2[((NH * DH) / 8) * (HID / 16) * 32 * 2];   // B-frags
__device__ uint32_t g_wkp2[((NKV * DH) / 8) * (HID / 16) * 32 * 2];
__device__ uint32_t g_wvp2[((NKV * DH) / 8) * (HID / 16) * 32 * 2];
__device__ uint32_t g_wop2[(HID / 8) * ((NH * DH) / 16) * 32 * 2];

// ---------------------------------------------------------------------------
// Helpers
// ---------------------------------------------------------------------------
__device__ __forceinline__ uint32_t f2tf32(float f) {
    uint32_t u;
    asm("cvt.rna.tf32.f32 %0, %1;" : "=r"(u) : "f"(f));
    return u;
}
__device__ __forceinline__ float rtf(float f) { return __uint_as_float(f2tf32(f)); }

__device__ __forceinline__ void mma_tf32(float* d, const uint32_t* a, const uint32_t* b) {
    asm volatile(
        "mma.sync.aligned.m16n8k8.row.col.f32.tf32.tf32.f32 "
        "{%0,%1,%2,%3}, {%4,%5,%6,%7}, {%8,%9}, {%0,%1,%2,%3};\n"
        : "+f"(d[0]), "+f"(d[1]), "+f"(d[2]), "+f"(d[3])
        : "r"(a[0]), "r"(a[1]), "r"(a[2]), "r"(a[3]),
          "r"(b[0]), "r"(b[1]));
}

__device__ __forceinline__ void mma_f16(float* d, const uint32_t* a, const uint32_t* b) {
    asm volatile(
        "mma.sync.aligned.m16n8k16.row.col.f32.f16.f16.f32 "
        "{%0,%1,%2,%3}, {%4,%5,%6,%7}, {%8,%9}, {%0,%1,%2,%3};\n"
        : "+f"(d[0]), "+f"(d[1]), "+f"(d[2]), "+f"(d[3])
        : "r"(a[0]), "r"(a[1]), "r"(a[2]), "r"(a[3]),
          "r"(b[0]), "r"(b[1]));
}

__device__ __forceinline__ uint32_t packh2(float a, float b) {
    __half2 h = __floats2half2_rn(a, b);
    return *(uint32_t*)&h;
}

__device__ __forceinline__ uint32_t smem_u32(const void* p) {
    return (uint32_t)__cvta_generic_to_shared(p);
}

#define CP16(dst, src) asm volatile("cp.async.cg.shared.global [%0], [%1], 16;" :: "r"(dst), "l"(src))
#define CP_COMMIT()    asm volatile("cp.async.commit_group;")
#define CP_WAIT(n)     asm volatile("cp.async.wait_group %0;" :: "n"(n))

// ---------------------------------------------------------------------------
// Prep: permute fp32 -> fragment-contiguous fp16 layouts.
// A unit (mt, kt16, lane): 4 u32 = {(r,kb,kb+1),(r+8,kb,kb+1),(r,kb+8,kb+9),(r+8,kb+8,kb+9)}
//   with r = mt*16 + lane/4, kb = kt*16 + 2*(lane%4)
// B unit (nt, kt16, lane): 2 u32 = {(kb,kb+1 @ n),(kb+8,kb+9 @ n)}, n = nt*8 + lane/4
// ---------------------------------------------------------------------------
__global__ __launch_bounds__(256) void permuteA_h(
    const float* __restrict__ in, uint32_t* __restrict__ out, int M, int K)
{
    int id = blockIdx.x * 256 + threadIdx.x;
    int KT = K >> 4;
    int total = (M >> 4) * KT * 32;
    if (id >= total) return;
    int lane = id & 31;
    int kt   = (id >> 5) % KT;
    int mt   = (id >> 5) / KT;
    int r  = mt * 16 + (lane >> 2);
    int cb = kt * 16 + 2 * (lane & 3);
    const float* p0 = in + (size_t)r * K + cb;
    const float* p1 = p0 + (size_t)8 * K;
    uint4 v;
    v.x = packh2(p0[0], p0[1]);
    v.y = packh2(p1[0], p1[1]);
    v.z = packh2(p0[8], p0[9]);
    v.w = packh2(p1[8], p1[9]);
    ((uint4*)out)[id] = v;
}

__global__ __launch_bounds__(256) void permuteB_h(
    const float* __restrict__ in, uint32_t* __restrict__ out, int K, int N)
{
    int id = blockIdx.x * 256 + threadIdx.x;
    int KT = K >> 4;
    int total = (N >> 3) * KT * 32;
    if (id >= total) return;
    int lane = id & 31;
    int kt   = (id >> 5) % KT;
    int nt   = (id >> 5) / KT;
    int n  = nt * 8 + (lane >> 2);
    int kb = kt * 16 + 2 * (lane & 3);
    uint2 v;
    v.x = packh2(in[(size_t)kb * N + n],       in[(size_t)(kb + 1) * N + n]);
    v.y = packh2(in[(size_t)(kb + 8) * N + n], in[(size_t)(kb + 9) * N + n]);
    ((uint2*)out)[id] = v;
}

// ---------------------------------------------------------------------------
// FP16 GEMM on permuted operands. Block 128x256, 256 threads (8 warps, 64x64
// warp tiles), BK=64 (4 k16 steps) per stage, 3-stage cp.async.
// Output fp32 row-major; round_out=1 applies rna->tf32 rounding.
// ---------------------------------------------------------------------------
#define HSA 16384                 // 128x64 half
#define HSB 32768                 // 256x64 half
#define HSTG (HSA + HSB)
#define HNSTG 3
#define HSMEM (HNSTG * HSTG)      // 147,456

__global__ __launch_bounds__(256, 1) void gemm_h(
    const uint32_t* __restrict__ Ap, const uint32_t* __restrict__ Bp,
    float* __restrict__ C, int M, int N, int K, int round_out)
{
    extern __shared__ __align__(16) char smem[];

    const int tid  = threadIdx.x;
    const int lane = tid & 31;
    const int w    = tid >> 5;
    const int wm   = (w >> 2) * 64;
    const int wn   = (w & 3) * 64;
    const int bm   = blockIdx.y * 128;
    const int bn   = blockIdx.x * 256;

    const int KT16 = K >> 4;
    const int NT   = K >> 6;
    const int mt0  = bm >> 4;
    const int nt0  = bn >> 3;

    auto fill = [&](int buf, int kt0) {
        char* sA = smem + buf * HSTG;
        char* sB = sA + HSA;
#pragma unroll
        for (int i = 0; i < 4; i++) {          // A: 1024 x 16B
            int id = i * 256 + tid;
            int mt_i = id >> 7, kt_i = (id >> 5) & 3, ln = id & 31;
            size_t g = (((size_t)(mt0 + mt_i) * KT16 + kt0 + kt_i) * 32 + ln);
            CP16(smem_u32(sA + id * 16), (const char*)Ap + g * 16);
        }
#pragma unroll
        for (int i = 0; i < 8; i++) {          // B: 2048 x 16B
            int id = i * 256 + tid;
            int nt_i = id >> 6, kt_i = (id >> 4) & 3, u = id & 15;
            size_t g = (((size_t)(nt0 + nt_i) * KT16 + kt0 + kt_i) * 32 + 2 * u);
            CP16(smem_u32(sB + id * 16), (const char*)Bp + g * 8);
        }
    };

    fill(0, 0); CP_COMMIT();
    fill(1, 4); CP_COMMIT();

    float acc[4][8][4] = {};

    for (int t = 0; t < NT; t++) {
        CP_WAIT(1);
        __syncthreads();
        if (t + 2 < NT) fill((t + 2) % HNSTG, (t + 2) * 4);
        CP_COMMIT();

        const char* sA = smem + (t % HNSTG) * HSTG;
        const char* sB = sA + HSA;

#pragma unroll
        for (int kt = 0; kt < 4; kt++) {
            uint4 af[4];
            uint2 bf[8];
#pragma unroll
            for (int mi = 0; mi < 4; mi++) {
                int mt_t = (wm >> 4) + mi;
                af[mi] = *(const uint4*)(sA + (((mt_t * 4 + kt) * 32 + lane) << 4));
            }
#pragma unroll
            for (int ni = 0; ni < 8; ni++) {
                int nt_t = (wn >> 3) + ni;
                bf[ni] = *(const uint2*)(sB + (((nt_t * 4 + kt) * 32 + lane) << 3));
            }
#pragma unroll
            for (int mi = 0; mi < 4; mi++)
#pragma unroll
                for (int ni = 0; ni < 8; ni++)
                    mma_f16(acc[mi][ni], (const uint32_t*)&af[mi], (const uint32_t*)&bf[ni]);
        }
    }

#pragma unroll
    for (int mi = 0; mi < 4; mi++) {
        int r0 = bm + wm + mi * 16 + (lane >> 2);
#pragma unroll
        for (int ni = 0; ni < 8; ni++) {
            int c = bn + wn + ni * 8 + 2 * (lane & 3);
            float v0 = acc[mi][ni][0], v1 = acc[mi][ni][1];
            float v2 = acc[mi][ni][2], v3 = acc[mi][ni][3];
            if (round_out) { v0 = rtf(v0); v1 = rtf(v1); v2 = rtf(v2); v3 = rtf(v3); }
            *(float2*)(C + (size_t)r0 * N + c)       = make_float2(v0, v1);
            *(float2*)(C + (size_t)(r0 + 8) * N + c) = make_float2(v2, v3);
        }
    }
}

// ---------------------------------------------------------------------------
// RoPE (interleaved pairs), in-place; outputs rna-rounded to tf32.  (R7 verbatim)
// ---------------------------------------------------------------------------
__global__ __launch_bounds__(256) void rope_kernel(
    float* __restrict__ Q, float* __restrict__ Kt,
    const float* __restrict__ freqs)
{
    const int QP = ROWS * NH * (DH / 2);
    const int KP = ROWS * NKV * (DH / 2);
    int idx = blockIdx.x * blockDim.x + threadIdx.x;
    if (idx < QP) {
        int i   = idx & 63;
        int h   = (idx >> 6) & (NH - 1);
        int row = idx >> 10;
        int s   = row & (S_LEN - 1);
        float c  = freqs[s * 128 + 2 * i];
        float sn = freqs[s * 128 + 2 * i + 1];
        float* p = Q + (size_t)row * (NH * DH) + h * DH + 2 * i;
        float xr = p[0], xi = p[1];
        p[0] = rtf(xr * c - xi * sn);
        p[1] = rtf(xr * sn + xi * c);
    } else if (idx < QP + KP) {
        int j   = idx - QP;
        int i   = j & 63;
        int h   = (j >> 6) & (NKV - 1);
        int row = j >> 8;
        int s   = row & (S_LEN - 1);
        float c  = freqs[s * 128 + 2 * i];
        float sn = freqs[s * 128 + 2 * i + 1];
        float* p = Kt + (size_t)row * (NKV * DH) + h * DH + 2 * i;
        float xr = p[0], xi = p[1];
        p[0] = rtf(xr * c - xi * sn);
        p[1] = rtf(xr * sn + xi * c);
    }
}

// ---------------------------------------------------------------------------
// TF32 legacy-mma flash attention (causal, GQA) — R7 verbatim (passing).
// ---------------------------------------------------------------------------
#define AQ 128
#define AK 32
#define QSTR 132
#define KSTR 132
#define VSTR 136
#define PSTR 36

__global__ __launch_bounds__(256) void attn_tc(
    const float* __restrict__ Q, const float* __restrict__ K,
    const float* __restrict__ V, float* __restrict__ O)
{
    extern __shared__ float sh[];
    float* Qs = sh;
    float* Ks = Qs + AQ * QSTR;
    float* Vs = Ks + 2 * AK * KSTR;
    float* Ps = Vs + 2 * AK * VSTR;

    const int qt  = gridDim.x - 1 - blockIdx.x;
    const int bh  = blockIdx.y;
    const int b   = bh >> 4;
    const int h   = bh & 15;
    const int kvh = h >> 2;
    const int tid = threadIdx.x;
    const int lane = tid & 31;
    const int w    = tid >> 5;

    const float scale = 0.08838834764831845f;

    const size_t qbase = ((size_t)(b * S_LEN + qt * AQ)) * (NH * DH) + h * DH;
    for (int t = tid; t < AQ * DH / 4; t += 256) {
        int r = t >> 5, c = (t & 31) * 4;
        float4 v = *(const float4*)(Q + qbase + (size_t)r * (NH * DH) + c);
        v.x = rtf(v.x * scale); v.y = rtf(v.y * scale);
        v.z = rtf(v.z * scale); v.w = rtf(v.w * scale);
        *(float4*)&Qs[r * QSTR + c] = v;
    }

    const size_t kvbase = ((size_t)(b * S_LEN)) * (NKV * DH) + kvh * DH;

    auto issueKV = [&](int buf, int kt) {
        float* ks = Ks + buf * AK * KSTR;
        float* vs = Vs + buf * AK * VSTR;
#pragma unroll
        for (int i = 0; i < 4; i++) {
            int id = tid + i * 256;
            int r = id >> 5, c = (id & 31) * 4;
            size_t g = kvbase + (size_t)(kt * AK + r) * (NKV * DH) + c;
            CP16(smem_u32(ks + r * KSTR + c), K + g);
            CP16(smem_u32(vs + r * VSTR + c), V + g);
        }
    };

    const int KT = 4 * qt + 4;
    issueKV(0, 0); CP_COMMIT();

    const int rA = w * 16 + (lane >> 2);
    const int q0 = qt * AQ + rA;
    const int q1 = q0 + 8;

    float m0 = -INFINITY, m1 = -INFINITY, l0 = 0.f, l1 = 0.f;
    float oacc[16][4] = {};

    for (int kt = 0; kt < KT; kt++) {
        __syncthreads();
        if (kt + 1 < KT) issueKV((kt + 1) & 1, kt + 1);
        CP_COMMIT();
        CP_WAIT(1);
        __syncthreads();

        const float* ks = Ks + (kt & 1) * AK * KSTR;
        const float* vs = Vs + (kt & 1) * AK * VSTR;

        float sacc[4][4] = {};
#pragma unroll
        for (int kk = 0; kk < DH; kk += 8) {
            uint32_t af[4], bf[4][2];
            int c = kk + (lane & 3);
            af[0] = __float_as_uint(Qs[rA * QSTR + c]);
            af[1] = __float_as_uint(Qs[(rA + 8) * QSTR + c]);
            af[2] = __float_as_uint(Qs[rA * QSTR + c + 4]);
            af[3] = __float_as_uint(Qs[(rA + 8) * QSTR + c + 4]);
#pragma unroll
            for (int ni = 0; ni < 4; ni++) {
                int key = ni * 8 + (lane >> 2);
                bf[ni][0] = __float_as_uint(ks[key * KSTR + c]);
                bf[ni][1] = __float_as_uint(ks[key * KSTR + c + 4]);
            }
#pragma unroll
            for (int ni = 0; ni < 4; ni++) mma_tf32(sacc[ni], af, bf[ni]);
        }

        if (kt >= 4 * qt) {
            int kb = kt * AK + 2 * (lane & 3);
#pragma unroll
            for (int ni = 0; ni < 4; ni++) {
                int kc = kb + ni * 8;
                if (kc     > q0) sacc[ni][0] = -INFINITY;
                if (kc + 1 > q0) sacc[ni][1] = -INFINITY;
                if (kc     > q1) sacc[ni][2] = -INFINITY;
                if (kc + 1 > q1) sacc[ni][3] = -INFINITY;
            }
        }

        float t0 = -INFINITY, t1 = -INFINITY;
#pragma unroll
        for (int ni = 0; ni < 4; ni++) {
            t0 = fmaxf(t0, fmaxf(sacc[ni][0], sacc[ni][1]));
            t1 = fmaxf(t1, fmaxf(sacc[ni][2], sacc[ni][3]));
        }
        t0 = fmaxf(t0, __shfl_xor_sync(0xffffffffu, t0, 1));
        t0 = fmaxf(t0, __shfl_xor_sync(0xffffffffu, t0, 2));
        t1 = fmaxf(t1, __shfl_xor_sync(0xffffffffu, t1, 1));
        t1 = fmaxf(t1, __shfl_xor_sync(0xffffffffu, t1, 2));

        float n0 = fmaxf(m0, t0), n1 = fmaxf(m1, t1);
        float c0 = __expf(m0 - n0), c1 = __expf(m1 - n1);
        float s0 = 0.f, s1 = 0.f;
#pragma unroll
        for (int ni = 0; ni < 4; ni++) {
            sacc[ni][0] = __expf(sacc[ni][0] - n0);
            sacc[ni][1] = __expf(sacc[ni][1] - n0);
            sacc[ni][2] = __expf(sacc[ni][2] - n1);
            sacc[ni][3] = __expf(sacc[ni][3] - n1);
            s0 += sacc[ni][0] + sacc[ni][1];
            s1 += sacc[ni][2] + sacc[ni][3];
        }
        s0 += __shfl_xor_sync(0xffffffffu, s0, 1);
        s0 += __shfl_xor_sync(0xffffffffu, s0, 2);
        s1 += __shfl_xor_sync(0xffffffffu, s1, 1);
        s1 += __shfl_xor_sync(0xffffffffu, s1, 2);
        l0 = l0 * c0 + s0;  l1 = l1 * c1 + s1;
        m0 = n0;            m1 = n1;

#pragma unroll
        for (int ni = 0; ni < 16; ni++) {
            oacc[ni][0] *= c0; oacc[ni][1] *= c0;
            oacc[ni][2] *= c1; oacc[ni][3] *= c1;
        }

#pragma unroll
        for (int ni = 0; ni < 4; ni++) {
            int c = ni * 8 + 2 * (lane & 3);
            Ps[rA * PSTR + c]           = sacc[ni][0];
            Ps[rA * PSTR + c + 1]       = sacc[ni][1];
            Ps[(rA + 8) * PSTR + c]     = sacc[ni][2];
            Ps[(rA + 8) * PSTR + c + 1] = sacc[ni][3];
        }
        __syncwarp();

#pragma unroll
        for (int kk = 0; kk < AK; kk += 8) {
            uint32_t af[4];
            int c = kk + (lane & 3);
            af[0] = f2tf32(Ps[rA * PSTR + c]);
            af[1] = f2tf32(Ps[(rA + 8) * PSTR + c]);
            af[2] = f2tf32(Ps[rA * PSTR + c + 4]);
            af[3] = f2tf32(Ps[(rA + 8) * PSTR + c + 4]);
#pragma unroll
            for (int ni = 0; ni < 16; ni++) {
                uint32_t bf[2];
                int d = ni * 8 + (lane >> 2);
                bf[0] = __float_as_uint(vs[(kk + (lane & 3)) * VSTR + d]);
                bf[1] = __float_as_uint(vs[(kk + 4 + (lane & 3)) * VSTR + d]);
                mma_tf32(oacc[ni], af, bf);
            }
        }
    }

    float i0 = 1.f / l0, i1 = 1.f / l1;
#pragma unroll
    for (int ni = 0; ni < 16; ni++) {
        int c = ni * 8 + 2 * (lane & 3);
        *(float2*)(O + qbase + (size_t)rA * (NH * DH) + c) =
            make_float2(rtf(oacc[ni][0] * i0), rtf(oacc[ni][1] * i0));
        *(float2*)(O + qbase + (size_t)(rA + 8) * (NH * DH) + c) =
            make_float2(rtf(oacc[ni][2] * i1), rtf(oacc[ni][3] * i1));
    }
}

// ---------------------------------------------------------------------------
// Launch
// ---------------------------------------------------------------------------
extern "C" void kernel_launch(void* const* d_in, const int* in_sizes, int n_in,
                              void* d_out, int out_size)
{
    const float* x     = (const float*)d_in[0];
    const float* freqs = (const float*)d_in[1];
    const float* wq    = (const float*)d_in[2];
    const float* wk    = (const float*)d_in[3];
    const float* wv    = (const float*)d_in[4];
    const float* wo    = (const float*)d_in[5];
    float* out = (float*)d_out;

    float *Qd, *Kd, *Vd, *Od;
    uint32_t *xp4, *Op4, *wqp2, *wkp2, *wvp2, *wop2;
    cudaGetSymbolAddress((void**)&Qd, g_Q);
    cudaGetSymbolAddress((void**)&Kd, g_K);
    cudaGetSymbolAddress((void**)&Vd, g_V);
    cudaGetSymbolAddress((void**)&Od, g_O);
    cudaGetSymbolAddress((void**)&xp4, g_xp4);
    cudaGetSymbolAddress((void**)&Op4, g_Op4);
    cudaGetSymbolAddress((void**)&wqp2, g_wqp2);
    cudaGetSymbolAddress((void**)&wkp2, g_wkp2);
    cudaGetSymbolAddress((void**)&wvp2, g_wvp2);
    cudaGetSymbolAddress((void**)&wop2, g_wop2);

    // Prep: permute + round to fp16 fragments
    {
        int n = (ROWS / 16) * (HID / 16) * 32;
        permuteA_h<<<(n + 255) / 256, 256>>>(x, xp4, ROWS, HID);
        n = ((NH * DH) / 8) * (HID / 16) * 32;
        permuteB_h<<<(n + 255) / 256, 256>>>(wq, wqp2, HID, NH * DH);
        n = ((NKV * DH) / 8) * (HID / 16) * 32;
        permuteB_h<<<(n + 255) / 256, 256>>>(wk, wkp2, HID, NKV * DH);
        permuteB_h<<<(n + 255) / 256, 256>>>(wv, wvp2, HID, NKV * DH);
        n = (HID / 8) * ((NH * DH) / 16) * 32;
        permuteB_h<<<(n + 255) / 256, 256>>>(wo, wop2, NH * DH, HID);
    }

    cudaFuncSetAttribute(gemm_h, cudaFuncAttributeMaxDynamicSharedMemorySize, HSMEM);

    // QKV projections (fp16 mma, tf32-rounded fp32 outputs)
    {
        dim3 gq(HID / 256, ROWS / 128);            // (8, 32)
        gemm_h<<<gq, 256, HSMEM>>>(xp4, wqp2, Qd, ROWS, NH * DH, HID, 1);
        dim3 gk((NKV * DH) / 256, ROWS / 128);     // (2, 32)
        gemm_h<<<gk, 256, HSMEM>>>(xp4, wkp2, Kd, ROWS, NKV * DH, HID, 1);
        gemm_h<<<gk, 256, HSMEM>>>(xp4, wvp2, Vd, ROWS, NKV * DH, HID, 1);
    }

    // RoPE
    {
        int total = ROWS * NH * (DH / 2) + ROWS * NKV * (DH / 2);
        rope_kernel<<<(total + 255) / 256, 256>>>(Qd, Kd, freqs);
    }

    // Attention (tf32 path, proven)
    {
        const int attn_smem = (AQ * QSTR + 2 * AK * KSTR + 2 * AK * VSTR + AQ * PSTR) * 4;
        cudaFuncSetAttribute(attn_tc, cudaFuncAttributeMaxDynamicSharedMemorySize, attn_smem);
        dim3 ga(S_LEN / AQ, B_SZ * NH);
        attn_tc<<<ga, 256, attn_smem>>>(Qd, Kd, Vd, Od);
    }

    // O permute -> fp16 frags -> output projection (raw fp32 out)
    {
        int n = (ROWS / 16) * ((NH * DH) / 16) * 32;
        permuteA_h<<<(n + 255) / 256, 256>>>(Od, Op4, ROWS, NH * DH);
        dim3 go(HID / 256, ROWS / 128);
        gemm_h<<<go, 256, HSMEM>>>(Op4, wop2, out, ROWS, HID, NH * DH, 0);
    }
}

// round 10
// speedup vs baseline: 10.2021x; 1.3003x over previous
#include <cuda_runtime.h>
#include <cuda_fp16.h>
#include <math.h>
#include <stdint.h>

// Problem constants
#define B_SZ   2
#define S_LEN  2048
#define HID    2048
#define NH     16
#define NKV    4
#define DH     128
#define GROUPS (NH / NKV)
#define ROWS   (B_SZ * S_LEN)        // 4096

// Scratch
__device__ __half   g_Qh[ROWS * NH * DH];            // Q row-major half
__device__ __half   g_Kh[ROWS * NKV * DH];           // K row-major half
__device__ __half   g_Vt[B_SZ * NKV * DH * S_LEN];   // V transposed [b][kvh][d][s]
__device__ uint32_t g_xp4[(ROWS / 16) * (HID / 16) * 32 * 4];        // x A-frag
__device__ uint32_t g_Op4[(ROWS / 16) * ((NH * DH) / 16) * 32 * 4];  // attn-O A-frag
__device__ uint32_t g_wqp2[((NH * DH) / 8) * (HID / 16) * 32 * 2];   // B-frags
__device__ uint32_t g_wkp2[((NKV * DH) / 8) * (HID / 16) * 32 * 2];
__device__ uint32_t g_wvp2[((NKV * DH) / 8) * (HID / 16) * 32 * 2];
__device__ uint32_t g_wop2[(HID / 8) * ((NH * DH) / 16) * 32 * 2];

// ---------------------------------------------------------------------------
// Helpers
// ---------------------------------------------------------------------------
__device__ __forceinline__ void mma_f16(float* d, const uint32_t* a, const uint32_t* b) {
    asm volatile(
        "mma.sync.aligned.m16n8k16.row.col.f32.f16.f16.f32 "
        "{%0,%1,%2,%3}, {%4,%5,%6,%7}, {%8,%9}, {%0,%1,%2,%3};\n"
        : "+f"(d[0]), "+f"(d[1]), "+f"(d[2]), "+f"(d[3])
        : "r"(a[0]), "r"(a[1]), "r"(a[2]), "r"(a[3]),
          "r"(b[0]), "r"(b[1]));
}

__device__ __forceinline__ uint32_t packh2(float a, float b) {
    __half2 h = __floats2half2_rn(a, b);
    return *(uint32_t*)&h;
}

__device__ __forceinline__ uint32_t smem_u32(const void* p) {
    return (uint32_t)__cvta_generic_to_shared(p);
}

#define CP16(dst, src) asm volatile("cp.async.cg.shared.global [%0], [%1], 16;" :: "r"(dst), "l"(src))
#define CP_COMMIT()    asm volatile("cp.async.commit_group;")
#define CP_WAIT(n)     asm volatile("cp.async.wait_group %0;" :: "n"(n))

// ---------------------------------------------------------------------------
// Prep: permute fp32 -> fragment-contiguous fp16 layouts.
// ---------------------------------------------------------------------------
__global__ __launch_bounds__(256) void permuteA_h(
    const float* __restrict__ in, uint32_t* __restrict__ out, int M, int K)
{
    int id = blockIdx.x * 256 + threadIdx.x;
    int KT = K >> 4;
    int total = (M >> 4) * KT * 32;
    if (id >= total) return;
    int lane = id & 31;
    int kt   = (id >> 5) % KT;
    int mt   = (id >> 5) / KT;
    int r  = mt * 16 + (lane >> 2);
    int cb = kt * 16 + 2 * (lane & 3);
    const float* p0 = in + (size_t)r * K + cb;
    const float* p1 = p0 + (size_t)8 * K;
    uint4 v;
    v.x = packh2(p0[0], p0[1]);
    v.y = packh2(p1[0], p1[1]);
    v.z = packh2(p0[8], p0[9]);
    v.w = packh2(p1[8], p1[9]);
    ((uint4*)out)[id] = v;
}

__global__ __launch_bounds__(256) void permuteB_h(
    const float* __restrict__ in, uint32_t* __restrict__ out, int K, int N)
{
    int id = blockIdx.x * 256 + threadIdx.x;
    int KT = K >> 4;
    int total = (N >> 3) * KT * 32;
    if (id >= total) return;
    int lane = id & 31;
    int kt   = (id >> 5) % KT;
    int nt   = (id >> 5) / KT;
    int n  = nt * 8 + (lane >> 2);
    int kb = kt * 16 + 2 * (lane & 3);
    uint2 v;
    v.x = packh2(in[(size_t)kb * N + n],       in[(size_t)(kb + 1) * N + n]);
    v.y = packh2(in[(size_t)(kb + 8) * N + n], in[(size_t)(kb + 9) * N + n]);
    ((uint2*)out)[id] = v;
}

// ---------------------------------------------------------------------------
// FP16 GEMM on permuted operands. Block 128x256, 256 threads (8 warps, 64x64
// warp tiles), BK=64 (4 k16 steps) per stage, 3-stage cp.async.
// mode: 0 = fp32 row-major out, 1 = half row-major out, 2 = half V-transpose.
// ---------------------------------------------------------------------------
#define HSA 16384
#define HSB 32768
#define HSTG (HSA + HSB)
#define HNSTG 3
#define HSMEM (HNSTG * HSTG)      // 147,456

__global__ __launch_bounds__(256, 1) void gemm_h(
    const uint32_t* __restrict__ Ap, const uint32_t* __restrict__ Bp,
    void* __restrict__ Cout, int M, int N, int K, int mode)
{
    extern __shared__ __align__(16) char smem[];

    const int tid  = threadIdx.x;
    const int lane = tid & 31;
    const int w    = tid >> 5;
    const int wm   = (w >> 2) * 64;
    const int wn   = (w & 3) * 64;
    const int bm   = blockIdx.y * 128;
    const int bn   = blockIdx.x * 256;

    const int KT16 = K >> 4;
    const int NT   = K >> 6;
    const int mt0  = bm >> 4;
    const int nt0  = bn >> 3;

    auto fill = [&](int buf, int kt0) {
        char* sA = smem + buf * HSTG;
        char* sB = sA + HSA;
#pragma unroll
        for (int i = 0; i < 4; i++) {
            int id = i * 256 + tid;
            int mt_i = id >> 7, kt_i = (id >> 5) & 3, ln = id & 31;
            size_t g = (((size_t)(mt0 + mt_i) * KT16 + kt0 + kt_i) * 32 + ln);
            CP16(smem_u32(sA + id * 16), (const char*)Ap + g * 16);
        }
#pragma unroll
        for (int i = 0; i < 8; i++) {
            int id = i * 256 + tid;
            int nt_i = id >> 6, kt_i = (id >> 4) & 3, u = id & 15;
            size_t g = (((size_t)(nt0 + nt_i) * KT16 + kt0 + kt_i) * 32 + 2 * u);
            CP16(smem_u32(sB + id * 16), (const char*)Bp + g * 8);
        }
    };

    fill(0, 0); CP_COMMIT();
    fill(1, 4); CP_COMMIT();

    float acc[4][8][4] = {};

    for (int t = 0; t < NT; t++) {
        CP_WAIT(1);
        __syncthreads();
        if (t + 2 < NT) fill((t + 2) % HNSTG, (t + 2) * 4);
        CP_COMMIT();

        const char* sA = smem + (t % HNSTG) * HSTG;
        const char* sB = sA + HSA;

#pragma unroll
        for (int kt = 0; kt < 4; kt++) {
            uint4 af[4];
            uint2 bf[8];
#pragma unroll
            for (int mi = 0; mi < 4; mi++) {
                int mt_t = (wm >> 4) + mi;
                af[mi] = *(const uint4*)(sA + (((mt_t * 4 + kt) * 32 + lane) << 4));
            }
#pragma unroll
            for (int ni = 0; ni < 8; ni++) {
                int nt_t = (wn >> 3) + ni;
                bf[ni] = *(const uint2*)(sB + (((nt_t * 4 + kt) * 32 + lane) << 3));
            }
#pragma unroll
            for (int mi = 0; mi < 4; mi++)
#pragma unroll
                for (int ni = 0; ni < 8; ni++)
                    mma_f16(acc[mi][ni], (const uint32_t*)&af[mi], (const uint32_t*)&bf[ni]);
        }
    }

#pragma unroll
    for (int mi = 0; mi < 4; mi++) {
        int r0 = bm + wm + mi * 16 + (lane >> 2);
#pragma unroll
        for (int ni = 0; ni < 8; ni++) {
            int c = bn + wn + ni * 8 + 2 * (lane & 3);
            float v0 = acc[mi][ni][0], v1 = acc[mi][ni][1];
            float v2 = acc[mi][ni][2], v3 = acc[mi][ni][3];
            if (mode == 0) {
                float* C = (float*)Cout;
                *(float2*)(C + (size_t)r0 * N + c)       = make_float2(v0, v1);
                *(float2*)(C + (size_t)(r0 + 8) * N + c) = make_float2(v2, v3);
            } else if (mode == 1) {
                __half* C = (__half*)Cout;
                *(uint32_t*)(C + (size_t)r0 * N + c)       = packh2(v0, v1);
                *(uint32_t*)(C + (size_t)(r0 + 8) * N + c) = packh2(v2, v3);
            } else {
                // V transpose: row r -> (b, s); col c -> (kvh, d)
                __half* Vt = (__half*)Cout;
                int b0 = r0 >> 11, s0 = r0 & 2047;
                int kvh = c >> 7;
                int d0 = c & 127;
                size_t base0 = (((size_t)(b0 * NKV + kvh) * DH + d0) * S_LEN);
                size_t base1 = base0 + S_LEN;   // d0+1 (d0 even, same kvh)
                Vt[base0 + s0]     = __float2half(v0);
                Vt[base1 + s0]     = __float2half(v1);
                Vt[base0 + s0 + 8] = __float2half(v2);
                Vt[base1 + s0 + 8] = __float2half(v3);
            }
        }
    }
}

// ---------------------------------------------------------------------------
// RoPE on half Q/K (fp32 math); Q additionally scaled by 1/sqrt(DH).
// ---------------------------------------------------------------------------
__global__ __launch_bounds__(256) void rope_h(
    __half* __restrict__ Q, __half* __restrict__ Kt,
    const float* __restrict__ freqs)
{
    const int QP = ROWS * NH * (DH / 2);
    const int KP = ROWS * NKV * (DH / 2);
    const float scale = 0.08838834764831845f;
    int idx = blockIdx.x * blockDim.x + threadIdx.x;
    if (idx < QP) {
        int i   = idx & 63;
        int h   = (idx >> 6) & (NH - 1);
        int row = idx >> 10;
        int s   = row & (S_LEN - 1);
        float c  = freqs[s * 128 + 2 * i];
        float sn = freqs[s * 128 + 2 * i + 1];
        __half2* p = (__half2*)(Q + (size_t)row * (NH * DH) + h * DH + 2 * i);
        float2 v = __half22float2(*p);
        *p = __floats2half2_rn((v.x * c - v.y * sn) * scale,
                               (v.x * sn + v.y * c) * scale);
    } else if (idx < QP + KP) {
        int j   = idx - QP;
        int i   = j & 63;
        int h   = (j >> 6) & (NKV - 1);
        int row = j >> 8;
        int s   = row & (S_LEN - 1);
        float c  = freqs[s * 128 + 2 * i];
        float sn = freqs[s * 128 + 2 * i + 1];
        __half2* p = (__half2*)(Kt + (size_t)row * (NKV * DH) + h * DH + 2 * i);
        float2 v = __half22float2(*p);
        *p = __floats2half2_rn(v.x * c - v.y * sn, v.x * sn + v.y * c);
    }
}

// ---------------------------------------------------------------------------
// FP16 flash attention (causal, GQA). Block = 128 queries of one (b,h),
// 256 threads (8 warps x 16 q-rows). Key tiles of 32, 2-stage cp.async.
// V pre-transposed globally; P register-direct into PV mma.
// Output written directly in O-proj A-fragment layout (g_Op4).
// ---------------------------------------------------------------------------
#define AQ 128
#define AK 32
#define QSH 136
#define VSH 40
#define ATT_SMEM ((AQ * QSH + 2 * AK * QSH + 2 * DH * VSH) * 2)

__global__ __launch_bounds__(256) void attn_h(
    const __half* __restrict__ Q, const __half* __restrict__ K,
    const __half* __restrict__ Vt, uint32_t* __restrict__ Op4)
{
    extern __shared__ __align__(16) __half sh[];
    __half* Qs  = sh;                        // [128][136]
    __half* Ks  = Qs + AQ * QSH;             // 2 x [32][136]
    __half* Vts = Ks + 2 * AK * QSH;         // 2 x [128][40]

    const int qt  = gridDim.x - 1 - blockIdx.x;
    const int bh  = blockIdx.y;
    const int b   = bh >> 4;
    const int h   = bh & 15;
    const int kvh = h >> 2;
    const int tid = threadIdx.x;
    const int lane = tid & 31;
    const int w    = tid >> 5;
    const int cq   = lane & 3;

    const size_t qbaseH = ((size_t)(b * S_LEN + qt * AQ)) * (NH * DH) + h * DH;
#pragma unroll
    for (int i = 0; i < 8; i++) {
        int t = i * 256 + tid;
        int r = t >> 4, u = t & 15;
        CP16(smem_u32(Qs + r * QSH + u * 8), Q + qbaseH + (size_t)r * (NH * DH) + u * 8);
    }

    const size_t kbaseH  = ((size_t)(b * S_LEN)) * (NKV * DH) + kvh * DH;
    const size_t vtbaseH = ((size_t)(b * NKV + kvh)) * DH * S_LEN;

    auto issueKV = [&](int buf, int kt) {
        __half* ks = Ks + buf * AK * QSH;
        __half* vs = Vts + buf * DH * VSH;
#pragma unroll
        for (int i = 0; i < 2; i++) {
            int id = i * 256 + tid;
            int r = id >> 4, u = id & 15;
            CP16(smem_u32(ks + r * QSH + u * 8),
                 K + kbaseH + (size_t)(kt * AK + r) * (NKV * DH) + u * 8);
        }
#pragma unroll
        for (int i = 0; i < 2; i++) {
            int id = i * 256 + tid;
            int d = id >> 2, u = id & 3;
            CP16(smem_u32(vs + d * VSH + u * 8),
                 Vt + vtbaseH + (size_t)d * S_LEN + kt * AK + u * 8);
        }
    };

    const int KT = 4 * qt + 4;
    issueKV(0, 0); CP_COMMIT();

    const int rA = w * 16 + (lane >> 2);
    const int q0 = qt * AQ + rA;
    const int q1 = q0 + 8;

    float m0 = -INFINITY, m1 = -INFINITY, l0 = 0.f, l1 = 0.f;
    float oacc[16][4] = {};

    for (int kt = 0; kt < KT; kt++) {
        __syncthreads();
        if (kt + 1 < KT) issueKV((kt + 1) & 1, kt + 1);
        CP_COMMIT();
        CP_WAIT(1);
        __syncthreads();

        const __half* ks = Ks + (kt & 1) * AK * QSH;
        const __half* vs = Vts + (kt & 1) * DH * VSH;

        // S = Q @ Ktile^T
        float sacc[4][4] = {};
        const __half* q0p = Qs + rA * QSH;
        const __half* q1p = q0p + 8 * QSH;
#pragma unroll
        for (int kk = 0; kk < DH; kk += 16) {
            uint32_t a[4];
            a[0] = *(const uint32_t*)(q0p + kk + 2 * cq);
            a[1] = *(const uint32_t*)(q1p + kk + 2 * cq);
            a[2] = *(const uint32_t*)(q0p + kk + 8 + 2 * cq);
            a[3] = *(const uint32_t*)(q1p + kk + 8 + 2 * cq);
#pragma unroll
            for (int ni = 0; ni < 4; ni++) {
                int key = ni * 8 + (lane >> 2);
                uint32_t bb[2];
                bb[0] = *(const uint32_t*)(ks + key * QSH + kk + 2 * cq);
                bb[1] = *(const uint32_t*)(ks + key * QSH + kk + 8 + 2 * cq);
                mma_f16(sacc[ni], a, bb);
            }
        }

        if (kt >= 4 * qt) {
            int kb = kt * AK + 2 * cq;
#pragma unroll
            for (int ni = 0; ni < 4; ni++) {
                int kc = kb + ni * 8;
                if (kc     > q0) sacc[ni][0] = -INFINITY;
                if (kc + 1 > q0) sacc[ni][1] = -INFINITY;
                if (kc     > q1) sacc[ni][2] = -INFINITY;
                if (kc + 1 > q1) sacc[ni][3] = -INFINITY;
            }
        }

        float t0 = -INFINITY, t1 = -INFINITY;
#pragma unroll
        for (int ni = 0; ni < 4; ni++) {
            t0 = fmaxf(t0, fmaxf(sacc[ni][0], sacc[ni][1]));
            t1 = fmaxf(t1, fmaxf(sacc[ni][2], sacc[ni][3]));
        }
        t0 = fmaxf(t0, __shfl_xor_sync(0xffffffffu, t0, 1));
        t0 = fmaxf(t0, __shfl_xor_sync(0xffffffffu, t0, 2));
        t1 = fmaxf(t1, __shfl_xor_sync(0xffffffffu, t1, 1));
        t1 = fmaxf(t1, __shfl_xor_sync(0xffffffffu, t1, 2));

        float n0 = fmaxf(m0, t0), n1 = fmaxf(m1, t1);
        float c0 = __expf(m0 - n0), c1 = __expf(m1 - n1);
        float s0 = 0.f, s1 = 0.f;
#pragma unroll
        for (int ni = 0; ni < 4; ni++) {
            sacc[ni][0] = __expf(sacc[ni][0] - n0);
            sacc[ni][1] = __expf(sacc[ni][1] - n0);
            sacc[ni][2] = __expf(sacc[ni][2] - n1);
            sacc[ni][3] = __expf(sacc[ni][3] - n1);
            s0 += sacc[ni][0] + sacc[ni][1];
            s1 += sacc[ni][2] + sacc[ni][3];
        }
        s0 += __shfl_xor_sync(0xffffffffu, s0, 1);
        s0 += __shfl_xor_sync(0xffffffffu, s0, 2);
        s1 += __shfl_xor_sync(0xffffffffu, s1, 1);
        s1 += __shfl_xor_sync(0xffffffffu, s1, 2);
        l0 = l0 * c0 + s0;  l1 = l1 * c1 + s1;
        m0 = n0;            m1 = n1;

#pragma unroll
        for (int ni = 0; ni < 16; ni++) {
            oacc[ni][0] *= c0; oacc[ni][1] *= c0;
            oacc[ni][2] *= c1; oacc[ni][3] *= c1;
        }

        // O += P @ Vtile : P packed straight from registers
#pragma unroll
        for (int s = 0; s < 2; s++) {
            uint32_t a[4];
            a[0] = packh2(sacc[2 * s][0],     sacc[2 * s][1]);
            a[1] = packh2(sacc[2 * s][2],     sacc[2 * s][3]);
            a[2] = packh2(sacc[2 * s + 1][0], sacc[2 * s + 1][1]);
            a[3] = packh2(sacc[2 * s + 1][2], sacc[2 * s + 1][3]);
#pragma unroll
            for (int ni = 0; ni < 16; ni++) {
                int d = ni * 8 + (lane >> 2);
                uint32_t bb[2];
                bb[0] = *(const uint32_t*)(vs + d * VSH + 16 * s + 2 * cq);
                bb[1] = *(const uint32_t*)(vs + d * VSH + 16 * s + 8 + 2 * cq);
                mma_f16(oacc[ni], a, bb);
            }
        }
    }

    // Epilogue: O-proj A-fragment layout. Column tile includes head offset!
    float i0 = 1.f / l0, i1 = 1.f / l1;
    const int mt = b * 128 + qt * 8 + w;
#pragma unroll
    for (int ni = 0; ni < 16; ni++) {
        int ktile = h * 8 + (ni >> 1);          // FIXED: += h*8
        int j = (ni & 1) ? 2 : 0;
        size_t idx = (((size_t)mt * ((NH * DH) / 16) + ktile) * 32 + lane) * 4;
        Op4[idx + j]     = packh2(oacc[ni][0] * i0, oacc[ni][1] * i0);
        Op4[idx + j + 1] = packh2(oacc[ni][2] * i1, oacc[ni][3] * i1);
    }
}

// ---------------------------------------------------------------------------
// Launch
// ---------------------------------------------------------------------------
extern "C" void kernel_launch(void* const* d_in, const int* in_sizes, int n_in,
                              void* d_out, int out_size)
{
    const float* x     = (const float*)d_in[0];
    const float* freqs = (const float*)d_in[1];
    const float* wq    = (const float*)d_in[2];
    const float* wk    = (const float*)d_in[3];
    const float* wv    = (const float*)d_in[4];
    const float* wo    = (const float*)d_in[5];
    float* out = (float*)d_out;

    __half *Qh, *Kh, *Vt;
    uint32_t *xp4, *Op4, *wqp2, *wkp2, *wvp2, *wop2;
    cudaGetSymbolAddress((void**)&Qh,  g_Qh);
    cudaGetSymbolAddress((void**)&Kh,  g_Kh);
    cudaGetSymbolAddress((void**)&Vt,  g_Vt);
    cudaGetSymbolAddress((void**)&xp4, g_xp4);
    cudaGetSymbolAddress((void**)&Op4, g_Op4);
    cudaGetSymbolAddress((void**)&wqp2, g_wqp2);
    cudaGetSymbolAddress((void**)&wkp2, g_wkp2);
    cudaGetSymbolAddress((void**)&wvp2, g_wvp2);
    cudaGetSymbolAddress((void**)&wop2, g_wop2);

    // Prep: permute + round to fp16 fragments
    {
        int n = (ROWS / 16) * (HID / 16) * 32;
        permuteA_h<<<(n + 255) / 256, 256>>>(x, xp4, ROWS, HID);
        n = ((NH * DH) / 8) * (HID / 16) * 32;
        permuteB_h<<<(n + 255) / 256, 256>>>(wq, wqp2, HID, NH * DH);
        n = ((NKV * DH) / 8) * (HID / 16) * 32;
        permuteB_h<<<(n + 255) / 256, 256>>>(wk, wkp2, HID, NKV * DH);
        permuteB_h<<<(n + 255) / 256, 256>>>(wv, wvp2, HID, NKV * DH);
        n = (HID / 8) * ((NH * DH) / 16) * 32;
        permuteB_h<<<(n + 255) / 256, 256>>>(wo, wop2, NH * DH, HID);
    }

    cudaFuncSetAttribute(gemm_h, cudaFuncAttributeMaxDynamicSharedMemorySize, HSMEM);

    // QKV projections
    {
        dim3 gq(HID / 256, ROWS / 128);            // (8, 32)
        gemm_h<<<gq, 256, HSMEM>>>(xp4, wqp2, Qh, ROWS, NH * DH, HID, 1);
        dim3 gk((NKV * DH) / 256, ROWS / 128);     // (2, 32)
        gemm_h<<<gk, 256, HSMEM>>>(xp4, wkp2, Kh, ROWS, NKV * DH, HID, 1);
        gemm_h<<<gk, 256, HSMEM>>>(xp4, wvp2, Vt, ROWS, NKV * DH, HID, 2);
    }

    // RoPE (Q gets softmax scale folded in)
    {
        int total = ROWS * NH * (DH / 2) + ROWS * NKV * (DH / 2);
        rope_h<<<(total + 255) / 256, 256>>>(Qh, Kh, freqs);
    }

    // Attention -> g_Op4 (O-proj A-fragment layout)
    {
        cudaFuncSetAttribute(attn_h, cudaFuncAttributeMaxDynamicSharedMemorySize, ATT_SMEM);
        dim3 ga(S_LEN / AQ, B_SZ * NH);            // (16, 32)
        attn_h<<<ga, 256, ATT_SMEM>>>(Qh, Kh, Vt, Op4);
    }

    // Output projection (fp32 out)
    {
        dim3 go(HID / 256, ROWS / 128);
        gemm_h<<<go, 256, HSMEM>>>(Op4, wop2, out, ROWS, HID, NH * DH, 0);
    }
}

// round 11
// speedup vs baseline: 11.1569x; 1.0936x over previous
#include <cuda_runtime.h>
#include <cuda_fp16.h>
#include <math.h>
#include <stdint.h>

// Problem constants
#define B_SZ   2
#define S_LEN  2048
#define HID    2048
#define NH     16
#define NKV    4
#define DH     128
#define GROUPS (NH / NKV)
#define ROWS   (B_SZ * S_LEN)        // 4096
#define NQKV   (NH * DH + 2 * NKV * DH)   // 3072

// Scratch
__device__ __half   g_Qh[ROWS * NH * DH];
__device__ __half   g_Kh[ROWS * NKV * DH];
__device__ __half   g_Vt[B_SZ * NKV * DH * S_LEN];   // [b][kvh][d][s]
__device__ uint32_t g_xp4[(ROWS / 16) * (HID / 16) * 32 * 4];
__device__ uint32_t g_Op4[(ROWS / 16) * ((NH * DH) / 16) * 32 * 4];
__device__ uint32_t g_wqkv2[(NQKV / 8) * (HID / 16) * 32 * 2];       // Q|K|V B-frags
__device__ uint32_t g_wop2[(HID / 8) * ((NH * DH) / 16) * 32 * 2];

// ---------------------------------------------------------------------------
// Helpers
// ---------------------------------------------------------------------------
__device__ __forceinline__ void mma_f16(float* d, const uint32_t* a, const uint32_t* b) {
    asm volatile(
        "mma.sync.aligned.m16n8k16.row.col.f32.f16.f16.f32 "
        "{%0,%1,%2,%3}, {%4,%5,%6,%7}, {%8,%9}, {%0,%1,%2,%3};\n"
        : "+f"(d[0]), "+f"(d[1]), "+f"(d[2]), "+f"(d[3])
        : "r"(a[0]), "r"(a[1]), "r"(a[2]), "r"(a[3]),
          "r"(b[0]), "r"(b[1]));
}

__device__ __forceinline__ uint32_t packh2(float a, float b) {
    __half2 h = __floats2half2_rn(a, b);
    return *(uint32_t*)&h;
}

__device__ __forceinline__ uint32_t smem_u32(const void* p) {
    return (uint32_t)__cvta_generic_to_shared(p);
}

#define CP16(dst, src) asm volatile("cp.async.cg.shared.global [%0], [%1], 16;" :: "r"(dst), "l"(src))
#define CP_COMMIT()    asm volatile("cp.async.commit_group;")
#define CP_WAIT(n)     asm volatile("cp.async.wait_group %0;" :: "n"(n))

// ---------------------------------------------------------------------------
// Prep: permute fp32 -> fragment-contiguous fp16 layouts.
// ---------------------------------------------------------------------------
__global__ __launch_bounds__(256) void permuteA_h(
    const float* __restrict__ in, uint32_t* __restrict__ out, int M, int K)
{
    int id = blockIdx.x * 256 + threadIdx.x;
    int KT = K >> 4;
    int total = (M >> 4) * KT * 32;
    if (id >= total) return;
    int lane = id & 31;
    int kt   = (id >> 5) % KT;
    int mt   = (id >> 5) / KT;
    int r  = mt * 16 + (lane >> 2);
    int cb = kt * 16 + 2 * (lane & 3);
    const float* p0 = in + (size_t)r * K + cb;
    const float* p1 = p0 + (size_t)8 * K;
    uint4 v;
    v.x = packh2(p0[0], p0[1]);
    v.y = packh2(p1[0], p1[1]);
    v.z = packh2(p0[8], p0[9]);
    v.w = packh2(p1[8], p1[9]);
    ((uint4*)out)[id] = v;
}

__global__ __launch_bounds__(256) void permuteB_h(
    const float* __restrict__ in, uint32_t* __restrict__ out, int K, int N)
{
    int id = blockIdx.x * 256 + threadIdx.x;
    int KT = K >> 4;
    int total = (N >> 3) * KT * 32;
    if (id >= total) return;
    int lane = id & 31;
    int kt   = (id >> 5) % KT;
    int nt   = (id >> 5) / KT;
    int n  = nt * 8 + (lane >> 2);
    int kb = kt * 16 + 2 * (lane & 3);
    uint2 v;
    v.x = packh2(in[(size_t)kb * N + n],       in[(size_t)(kb + 1) * N + n]);
    v.y = packh2(in[(size_t)(kb + 8) * N + n], in[(size_t)(kb + 9) * N + n]);
    ((uint2*)out)[id] = v;
}

// ---------------------------------------------------------------------------
// Shared GEMM mainloop macro-parts (128x256 tile, 8 warps, BK=64, 3 stages).
// ---------------------------------------------------------------------------
#define HSA 16384
#define HSB 32768
#define HSTG (HSA + HSB)
#define HNSTG 3
#define HSMEM (HNSTG * HSTG)      // 147,456

// Fused QKV projection: C = x @ [wq|wk|wv], N = 3072.
// Epilogue routes by bn: [0,2048) -> Qh, [2048,2560) -> Kh, [2560,3072) -> Vt.
__global__ __launch_bounds__(256, 1) void gemm_qkv(
    const uint32_t* __restrict__ Ap, const uint32_t* __restrict__ Bp,
    __half* __restrict__ Qh, __half* __restrict__ Kh, __half* __restrict__ Vt)
{
    extern __shared__ __align__(16) char smem[];

    const int tid  = threadIdx.x;
    const int lane = tid & 31;
    const int w    = tid >> 5;
    const int wm   = (w >> 2) * 64;
    const int wn   = (w & 3) * 64;
    const int bm   = blockIdx.y * 128;
    const int bn   = blockIdx.x * 256;

    const int K    = HID;
    const int KT16 = K >> 4;
    const int NT   = K >> 6;
    const int mt0  = bm >> 4;
    const int nt0  = bn >> 3;

    auto fill = [&](int buf, int kt0) {
        char* sA = smem + buf * HSTG;
        char* sB = sA + HSA;
#pragma unroll
        for (int i = 0; i < 4; i++) {
            int id = i * 256 + tid;
            int mt_i = id >> 7, kt_i = (id >> 5) & 3, ln = id & 31;
            size_t g = (((size_t)(mt0 + mt_i) * KT16 + kt0 + kt_i) * 32 + ln);
            CP16(smem_u32(sA + id * 16), (const char*)Ap + g * 16);
        }
#pragma unroll
        for (int i = 0; i < 8; i++) {
            int id = i * 256 + tid;
            int nt_i = id >> 6, kt_i = (id >> 4) & 3, u = id & 15;
            size_t g = (((size_t)(nt0 + nt_i) * KT16 + kt0 + kt_i) * 32 + 2 * u);
            CP16(smem_u32(sB + id * 16), (const char*)Bp + g * 8);
        }
    };

    fill(0, 0); CP_COMMIT();
    fill(1, 4); CP_COMMIT();

    float acc[4][8][4] = {};

    for (int t = 0; t < NT; t++) {
        CP_WAIT(1);
        __syncthreads();
        if (t + 2 < NT) fill((t + 2) % HNSTG, (t + 2) * 4);
        CP_COMMIT();

        const char* sA = smem + (t % HNSTG) * HSTG;
        const char* sB = sA + HSA;

#pragma unroll
        for (int kt = 0; kt < 4; kt++) {
            uint4 af[4];
            uint2 bf[8];
#pragma unroll
            for (int mi = 0; mi < 4; mi++) {
                int mt_t = (wm >> 4) + mi;
                af[mi] = *(const uint4*)(sA + (((mt_t * 4 + kt) * 32 + lane) << 4));
            }
#pragma unroll
            for (int ni = 0; ni < 8; ni++) {
                int nt_t = (wn >> 3) + ni;
                bf[ni] = *(const uint2*)(sB + (((nt_t * 4 + kt) * 32 + lane) << 3));
            }
#pragma unroll
            for (int mi = 0; mi < 4; mi++)
#pragma unroll
                for (int ni = 0; ni < 8; ni++)
                    mma_f16(acc[mi][ni], (const uint32_t*)&af[mi], (const uint32_t*)&bf[ni]);
        }
    }

    const int region = (bn < NH * DH) ? 0 : (bn < NH * DH + NKV * DH ? 1 : 2);

#pragma unroll
    for (int mi = 0; mi < 4; mi++) {
        int r0 = bm + wm + mi * 16 + (lane >> 2);
#pragma unroll
        for (int ni = 0; ni < 8; ni++) {
            int c = bn + wn + ni * 8 + 2 * (lane & 3);
            float v0 = acc[mi][ni][0], v1 = acc[mi][ni][1];
            float v2 = acc[mi][ni][2], v3 = acc[mi][ni][3];
            if (region == 0) {
                *(uint32_t*)(Qh + (size_t)r0 * (NH * DH) + c)       = packh2(v0, v1);
                *(uint32_t*)(Qh + (size_t)(r0 + 8) * (NH * DH) + c) = packh2(v2, v3);
            } else if (region == 1) {
                int ck = c - NH * DH;
                *(uint32_t*)(Kh + (size_t)r0 * (NKV * DH) + ck)       = packh2(v0, v1);
                *(uint32_t*)(Kh + (size_t)(r0 + 8) * (NKV * DH) + ck) = packh2(v2, v3);
            } else {
                int cc = c - (NH * DH + NKV * DH);
                int b0 = r0 >> 11, s0 = r0 & 2047;
                int kvh = cc >> 7;
                int d0 = cc & 127;
                size_t base0 = (((size_t)(b0 * NKV + kvh) * DH + d0) * S_LEN);
                size_t base1 = base0 + S_LEN;
                Vt[base0 + s0]     = __float2half(v0);
                Vt[base1 + s0]     = __float2half(v1);
                Vt[base0 + s0 + 8] = __float2half(v2);
                Vt[base1 + s0 + 8] = __float2half(v3);
            }
        }
    }
}

// O projection: fp32 row-major out (unchanged from R10 mode 0).
__global__ __launch_bounds__(256, 1) void gemm_o(
    const uint32_t* __restrict__ Ap, const uint32_t* __restrict__ Bp,
    float* __restrict__ C, int M, int N, int K)
{
    extern __shared__ __align__(16) char smem[];

    const int tid  = threadIdx.x;
    const int lane = tid & 31;
    const int w    = tid >> 5;
    const int wm   = (w >> 2) * 64;
    const int wn   = (w & 3) * 64;
    const int bm   = blockIdx.y * 128;
    const int bn   = blockIdx.x * 256;

    const int KT16 = K >> 4;
    const int NT   = K >> 6;
    const int mt0  = bm >> 4;
    const int nt0  = bn >> 3;

    auto fill = [&](int buf, int kt0) {
        char* sA = smem + buf * HSTG;
        char* sB = sA + HSA;
#pragma unroll
        for (int i = 0; i < 4; i++) {
            int id = i * 256 + tid;
            int mt_i = id >> 7, kt_i = (id >> 5) & 3, ln = id & 31;
            size_t g = (((size_t)(mt0 + mt_i) * KT16 + kt0 + kt_i) * 32 + ln);
            CP16(smem_u32(sA + id * 16), (const char*)Ap + g * 16);
        }
#pragma unroll
        for (int i = 0; i < 8; i++) {
            int id = i * 256 + tid;
            int nt_i = id >> 6, kt_i = (id >> 4) & 3, u = id & 15;
            size_t g = (((size_t)(nt0 + nt_i) * KT16 + kt0 + kt_i) * 32 + 2 * u);
            CP16(smem_u32(sB + id * 16), (const char*)Bp + g * 8);
        }
    };

    fill(0, 0); CP_COMMIT();
    fill(1, 4); CP_COMMIT();

    float acc[4][8][4] = {};

    for (int t = 0; t < NT; t++) {
        CP_WAIT(1);
        __syncthreads();
        if (t + 2 < NT) fill((t + 2) % HNSTG, (t + 2) * 4);
        CP_COMMIT();

        const char* sA = smem + (t % HNSTG) * HSTG;
        const char* sB = sA + HSA;

#pragma unroll
        for (int kt = 0; kt < 4; kt++) {
            uint4 af[4];
            uint2 bf[8];
#pragma unroll
            for (int mi = 0; mi < 4; mi++) {
                int mt_t = (wm >> 4) + mi;
                af[mi] = *(const uint4*)(sA + (((mt_t * 4 + kt) * 32 + lane) << 4));
            }
#pragma unroll
            for (int ni = 0; ni < 8; ni++) {
                int nt_t = (wn >> 3) + ni;
                bf[ni] = *(const uint2*)(sB + (((nt_t * 4 + kt) * 32 + lane) << 3));
            }
#pragma unroll
            for (int mi = 0; mi < 4; mi++)
#pragma unroll
                for (int ni = 0; ni < 8; ni++)
                    mma_f16(acc[mi][ni], (const uint32_t*)&af[mi], (const uint32_t*)&bf[ni]);
        }
    }

#pragma unroll
    for (int mi = 0; mi < 4; mi++) {
        int r0 = bm + wm + mi * 16 + (lane >> 2);
#pragma unroll
        for (int ni = 0; ni < 8; ni++) {
            int c = bn + wn + ni * 8 + 2 * (lane & 3);
            *(float2*)(C + (size_t)r0 * N + c) =
                make_float2(acc[mi][ni][0], acc[mi][ni][1]);
            *(float2*)(C + (size_t)(r0 + 8) * N + c) =
                make_float2(acc[mi][ni][2], acc[mi][ni][3]);
        }
    }
}

// ---------------------------------------------------------------------------
// RoPE on half Q/K (fp32 math); Q additionally scaled by 1/sqrt(DH).
// ---------------------------------------------------------------------------
__global__ __launch_bounds__(256) void rope_h(
    __half* __restrict__ Q, __half* __restrict__ Kt,
    const float* __restrict__ freqs)
{
    const int QP = ROWS * NH * (DH / 2);
    const int KP = ROWS * NKV * (DH / 2);
    const float scale = 0.08838834764831845f;
    int idx = blockIdx.x * blockDim.x + threadIdx.x;
    if (idx < QP) {
        int i   = idx & 63;
        int h   = (idx >> 6) & (NH - 1);
        int row = idx >> 10;
        int s   = row & (S_LEN - 1);
        float c  = freqs[s * 128 + 2 * i];
        float sn = freqs[s * 128 + 2 * i + 1];
        __half2* p = (__half2*)(Q + (size_t)row * (NH * DH) + h * DH + 2 * i);
        float2 v = __half22float2(*p);
        *p = __floats2half2_rn((v.x * c - v.y * sn) * scale,
                               (v.x * sn + v.y * c) * scale);
    } else if (idx < QP + KP) {
        int j   = idx - QP;
        int i   = j & 63;
        int h   = (j >> 6) & (NKV - 1);
        int row = j >> 8;
        int s   = row & (S_LEN - 1);
        float c  = freqs[s * 128 + 2 * i];
        float sn = freqs[s * 128 + 2 * i + 1];
        __half2* p = (__half2*)(Kt + (size_t)row * (NKV * DH) + h * DH + 2 * i);
        float2 v = __half22float2(*p);
        *p = __floats2half2_rn(v.x * c - v.y * sn, v.x * sn + v.y * c);
    }
}

// ---------------------------------------------------------------------------
// FP16 flash attention (causal, GQA) — R10 verbatim (passing).
// ---------------------------------------------------------------------------
#define AQ 128
#define AK 32
#define QSH 136
#define VSH 40
#define ATT_SMEM ((AQ * QSH + 2 * AK * QSH + 2 * DH * VSH) * 2)

__global__ __launch_bounds__(256) void attn_h(
    const __half* __restrict__ Q, const __half* __restrict__ K,
    const __half* __restrict__ Vt, uint32_t* __restrict__ Op4)
{
    extern __shared__ __align__(16) __half sh[];
    __half* Qs  = sh;
    __half* Ks  = Qs + AQ * QSH;
    __half* Vts = Ks + 2 * AK * QSH;

    const int qt  = gridDim.x - 1 - blockIdx.x;
    const int bh  = blockIdx.y;
    const int b   = bh >> 4;
    const int h   = bh & 15;
    const int kvh = h >> 2;
    const int tid = threadIdx.x;
    const int lane = tid & 31;
    const int w    = tid >> 5;
    const int cq   = lane & 3;

    const size_t qbaseH = ((size_t)(b * S_LEN + qt * AQ)) * (NH * DH) + h * DH;
#pragma unroll
    for (int i = 0; i < 8; i++) {
        int t = i * 256 + tid;
        int r = t >> 4, u = t & 15;
        CP16(smem_u32(Qs + r * QSH + u * 8), Q + qbaseH + (size_t)r * (NH * DH) + u * 8);
    }

    const size_t kbaseH  = ((size_t)(b * S_LEN)) * (NKV * DH) + kvh * DH;
    const size_t vtbaseH = ((size_t)(b * NKV + kvh)) * DH * S_LEN;

    auto issueKV = [&](int buf, int kt) {
        __half* ks = Ks + buf * AK * QSH;
        __half* vs = Vts + buf * DH * VSH;
#pragma unroll
        for (int i = 0; i < 2; i++) {
            int id = i * 256 + tid;
            int r = id >> 4, u = id & 15;
            CP16(smem_u32(ks + r * QSH + u * 8),
                 K + kbaseH + (size_t)(kt * AK + r) * (NKV * DH) + u * 8);
        }
#pragma unroll
        for (int i = 0; i < 2; i++) {
            int id = i * 256 + tid;
            int d = id >> 2, u = id & 3;
            CP16(smem_u32(vs + d * VSH + u * 8),
                 Vt + vtbaseH + (size_t)d * S_LEN + kt * AK + u * 8);
        }
    };

    const int KT = 4 * qt + 4;
    issueKV(0, 0); CP_COMMIT();

    const int rA = w * 16 + (lane >> 2);
    const int q0 = qt * AQ + rA;
    const int q1 = q0 + 8;

    float m0 = -INFINITY, m1 = -INFINITY, l0 = 0.f, l1 = 0.f;
    float oacc[16][4] = {};

    for (int kt = 0; kt < KT; kt++) {
        __syncthreads();
        if (kt + 1 < KT) issueKV((kt + 1) & 1, kt + 1);
        CP_COMMIT();
        CP_WAIT(1);
        __syncthreads();

        const __half* ks = Ks + (kt & 1) * AK * QSH;
        const __half* vs = Vts + (kt & 1) * DH * VSH;

        float sacc[4][4] = {};
        const __half* q0p = Qs + rA * QSH;
        const __half* q1p = q0p + 8 * QSH;
#pragma unroll
        for (int kk = 0; kk < DH; kk += 16) {
            uint32_t a[4];
            a[0] = *(const uint32_t*)(q0p + kk + 2 * cq);
            a[1] = *(const uint32_t*)(q1p + kk + 2 * cq);
            a[2] = *(const uint32_t*)(q0p + kk + 8 + 2 * cq);
            a[3] = *(const uint32_t*)(q1p + kk + 8 + 2 * cq);
#pragma unroll
            for (int ni = 0; ni < 4; ni++) {
                int key = ni * 8 + (lane >> 2);
                uint32_t bb[2];
                bb[0] = *(const uint32_t*)(ks + key * QSH + kk + 2 * cq);
                bb[1] = *(const uint32_t*)(ks + key * QSH + kk + 8 + 2 * cq);
                mma_f16(sacc[ni], a, bb);
            }
        }

        if (kt >= 4 * qt) {
            int kb = kt * AK + 2 * cq;
#pragma unroll
            for (int ni = 0; ni < 4; ni++) {
                int kc = kb + ni * 8;
                if (kc     > q0) sacc[ni][0] = -INFINITY;
                if (kc + 1 > q0) sacc[ni][1] = -INFINITY;
                if (kc     > q1) sacc[ni][2] = -INFINITY;
                if (kc + 1 > q1) sacc[ni][3] = -INFINITY;
            }
        }

        float t0 = -INFINITY, t1 = -INFINITY;
#pragma unroll
        for (int ni = 0; ni < 4; ni++) {
            t0 = fmaxf(t0, fmaxf(sacc[ni][0], sacc[ni][1]));
            t1 = fmaxf(t1, fmaxf(sacc[ni][2], sacc[ni][3]));
        }
        t0 = fmaxf(t0, __shfl_xor_sync(0xffffffffu, t0, 1));
        t0 = fmaxf(t0, __shfl_xor_sync(0xffffffffu, t0, 2));
        t1 = fmaxf(t1, __shfl_xor_sync(0xffffffffu, t1, 1));
        t1 = fmaxf(t1, __shfl_xor_sync(0xffffffffu, t1, 2));

        float n0 = fmaxf(m0, t0), n1 = fmaxf(m1, t1);
        float c0 = __expf(m0 - n0), c1 = __expf(m1 - n1);
        float s0 = 0.f, s1 = 0.f;
#pragma unroll
        for (int ni = 0; ni < 4; ni++) {
            sacc[ni][0] = __expf(sacc[ni][0] - n0);
            sacc[ni][1] = __expf(sacc[ni][1] - n0);
            sacc[ni][2] = __expf(sacc[ni][2] - n1);
            sacc[ni][3] = __expf(sacc[ni][3] - n1);
            s0 += sacc[ni][0] + sacc[ni][1];
            s1 += sacc[ni][2] + sacc[ni][3];
        }
        s0 += __shfl_xor_sync(0xffffffffu, s0, 1);
        s0 += __shfl_xor_sync(0xffffffffu, s0, 2);
        s1 += __shfl_xor_sync(0xffffffffu, s1, 1);
        s1 += __shfl_xor_sync(0xffffffffu, s1, 2);
        l0 = l0 * c0 + s0;  l1 = l1 * c1 + s1;
        m0 = n0;            m1 = n1;

#pragma unroll
        for (int ni = 0; ni < 16; ni++) {
            oacc[ni][0] *= c0; oacc[ni][1] *= c0;
            oacc[ni][2] *= c1; oacc[ni][3] *= c1;
        }

#pragma unroll
        for (int s = 0; s < 2; s++) {
            uint32_t a[4];
            a[0] = packh2(sacc[2 * s][0],     sacc[2 * s][1]);
            a[1] = packh2(sacc[2 * s][2],     sacc[2 * s][3]);
            a[2] = packh2(sacc[2 * s + 1][0], sacc[2 * s + 1][1]);
            a[3] = packh2(sacc[2 * s + 1][2], sacc[2 * s + 1][3]);
#pragma unroll
            for (int ni = 0; ni < 16; ni++) {
                int d = ni * 8 + (lane >> 2);
                uint32_t bb[2];
                bb[0] = *(const uint32_t*)(vs + d * VSH + 16 * s + 2 * cq);
                bb[1] = *(const uint32_t*)(vs + d * VSH + 16 * s + 8 + 2 * cq);
                mma_f16(oacc[ni], a, bb);
            }
        }
    }

    float i0 = 1.f / l0, i1 = 1.f / l1;
    const int mt = b * 128 + qt * 8 + w;
#pragma unroll
    for (int ni = 0; ni < 16; ni++) {
        int ktile = h * 8 + (ni >> 1);
        int j = (ni & 1) ? 2 : 0;
        size_t idx = (((size_t)mt * ((NH * DH) / 16) + ktile) * 32 + lane) * 4;
        Op4[idx + j]     = packh2(oacc[ni][0] * i0, oacc[ni][1] * i0);
        Op4[idx + j + 1] = packh2(oacc[ni][2] * i1, oacc[ni][3] * i1);
    }
}

// ---------------------------------------------------------------------------
// Launch
// ---------------------------------------------------------------------------
extern "C" void kernel_launch(void* const* d_in, const int* in_sizes, int n_in,
                              void* d_out, int out_size)
{
    const float* x     = (const float*)d_in[0];
    const float* freqs = (const float*)d_in[1];
    const float* wq    = (const float*)d_in[2];
    const float* wk    = (const float*)d_in[3];
    const float* wv    = (const float*)d_in[4];
    const float* wo    = (const float*)d_in[5];
    float* out = (float*)d_out;

    __half *Qh, *Kh, *Vt;
    uint32_t *xp4, *Op4, *wqkv2, *wop2;
    cudaGetSymbolAddress((void**)&Qh,  g_Qh);
    cudaGetSymbolAddress((void**)&Kh,  g_Kh);
    cudaGetSymbolAddress((void**)&Vt,  g_Vt);
    cudaGetSymbolAddress((void**)&xp4, g_xp4);
    cudaGetSymbolAddress((void**)&Op4, g_Op4);
    cudaGetSymbolAddress((void**)&wqkv2, g_wqkv2);
    cudaGetSymbolAddress((void**)&wop2, g_wop2);

    const int KT16 = HID / 16;   // 128

    // Prep: permute + round to fp16 fragments (wk/wv land after wq's nt range)
    {
        int n = (ROWS / 16) * (HID / 16) * 32;
        permuteA_h<<<(n + 255) / 256, 256>>>(x, xp4, ROWS, HID);
        n = ((NH * DH) / 8) * KT16 * 32;
        permuteB_h<<<(n + 255) / 256, 256>>>(wq, wqkv2, HID, NH * DH);
        n = ((NKV * DH) / 8) * KT16 * 32;
        uint32_t* wkDst = wqkv2 + (size_t)((NH * DH) / 8) * KT16 * 32 * 2;
        uint32_t* wvDst = wkDst + (size_t)((NKV * DH) / 8) * KT16 * 32 * 2;
        permuteB_h<<<(n + 255) / 256, 256>>>(wk, wkDst, HID, NKV * DH);
        permuteB_h<<<(n + 255) / 256, 256>>>(wv, wvDst, HID, NKV * DH);
        n = (HID / 8) * ((NH * DH) / 16) * 32;
        permuteB_h<<<(n + 255) / 256, 256>>>(wo, wop2, NH * DH, HID);
    }

    cudaFuncSetAttribute(gemm_qkv, cudaFuncAttributeMaxDynamicSharedMemorySize, HSMEM);
    cudaFuncSetAttribute(gemm_o,   cudaFuncAttributeMaxDynamicSharedMemorySize, HSMEM);

    // Fused QKV projection (one launch, 384 blocks)
    {
        dim3 g(NQKV / 256, ROWS / 128);            // (12, 32)
        gemm_qkv<<<g, 256, HSMEM>>>(xp4, wqkv2, Qh, Kh, Vt);
    }

    // RoPE (Q gets softmax scale folded in)
    {
        int total = ROWS * NH * (DH / 2) + ROWS * NKV * (DH / 2);
        rope_h<<<(total + 255) / 256, 256>>>(Qh, Kh, freqs);
    }

    // Attention -> g_Op4
    {
        cudaFuncSetAttribute(attn_h, cudaFuncAttributeMaxDynamicSharedMemorySize, ATT_SMEM);
        dim3 ga(S_LEN / AQ, B_SZ * NH);            // (16, 32)
        attn_h<<<ga, 256, ATT_SMEM>>>(Qh, Kh, Vt, Op4);
    }

    // Output projection
    {
        dim3 go(HID / 256, ROWS / 128);            // (8, 32)
        gemm_o<<<go, 256, HSMEM>>>(Op4, wop2, out, ROWS, HID, NH * DH);
    }
}